// round 6
// baseline (speedup 1.0000x reference)
#include <cuda_runtime.h>
#include <cuda_bf16.h>
#include <math.h>
#include <stdint.h>

// Problem constants
#define NEXP 8
#define TOPK 2
#define DH   1024
#define FH   4096
#define NTOK 4096
#define NSLOT (NTOK * TOPK)   // 8192

// ---------------- scratch (static __device__ — no allocations) -------------
__device__ __nv_bfloat16 g_X_hi[(size_t)NTOK * DH];
__device__ __nv_bfloat16 g_X_lo[(size_t)NTOK * DH];
__device__ __nv_bfloat16 g_fcwT_hi[(size_t)NEXP * FH * DH];  // [e][n(F)][k(D)]
__device__ __nv_bfloat16 g_fcwT_lo[(size_t)NEXP * FH * DH];
__device__ __nv_bfloat16 g_prjT_hi[(size_t)NEXP * DH * FH];  // [e][n(D)][k(F)]
__device__ __nv_bfloat16 g_prjT_lo[(size_t)NEXP * DH * FH];
__device__ __nv_bfloat16 g_H_hi[(size_t)NSLOT * FH];
__device__ __nv_bfloat16 g_H_lo[(size_t)NSLOT * FH];
__device__ float g_O[(size_t)NSLOT * DH];
__device__ int   g_count[NEXP];     // statically zero; re-zeroed by combine
__device__ int   g_cursor[NEXP];
__device__ int   g_off[NEXP + 1];
__device__ int   g_eid[NSLOT];
__device__ float g_wk[NSLOT];
__device__ int   g_tok[NSLOT];
__device__ float g_wt[NSLOT];
__device__ int   g_slot[NSLOT];

// ---------------- generic-PTX helpers ---------------------------------------
__device__ __forceinline__ uint32_t smem_u32(const void* p) {
    uint32_t a;
    asm("{ .reg .u64 t; cvta.to.shared.u64 t, %1; cvt.u32.u64 %0, t; }" : "=r"(a) : "l"(p));
    return a;
}
__device__ __forceinline__ void cp16(uint32_t dst, const void* src, int srcsize) {
    asm volatile("cp.async.cg.shared.global [%0], [%1], 16, %2;"
                 :: "r"(dst), "l"(src), "r"(srcsize) : "memory");
}
#define CP_COMMIT() asm volatile("cp.async.commit_group;" ::: "memory")
#define CP_WAIT1()  asm volatile("cp.async.wait_group 1;" ::: "memory")

__device__ __forceinline__ void ldsm_x4(uint32_t* r, uint32_t addr) {
    asm volatile("ldmatrix.sync.aligned.m8n8.x4.shared.b16 {%0,%1,%2,%3}, [%4];"
                 : "=r"(r[0]), "=r"(r[1]), "=r"(r[2]), "=r"(r[3]) : "r"(addr));
}
__device__ __forceinline__ void mma16816(float* d, const uint32_t* a, uint32_t b0, uint32_t b1) {
    asm volatile(
        "mma.sync.aligned.m16n8k16.row.col.f32.bf16.bf16.f32 "
        "{%0,%1,%2,%3}, {%4,%5,%6,%7}, {%8,%9}, {%0,%1,%2,%3};"
        : "+f"(d[0]), "+f"(d[1]), "+f"(d[2]), "+f"(d[3])
        : "r"(a[0]), "r"(a[1]), "r"(a[2]), "r"(a[3]), "r"(b0), "r"(b1));
}

__device__ __forceinline__ float gelu_new(float v) {
    const float c = 0.7978845608028654f;
    float u = c * (v + 0.044715f * v * v * v);
    return 0.5f * v * (1.0f + tanhf(u));
}
__device__ __forceinline__ uint32_t pack2(__nv_bfloat16 a, __nv_bfloat16 b) {
    return (uint32_t)__bfloat16_as_ushort(a) | ((uint32_t)__bfloat16_as_ushort(b) << 16);
}
__device__ __forceinline__ void split4(float4 v, uint2& hv, uint2& lv) {
    __nv_bfloat16 h0 = __float2bfloat16(v.x), h1 = __float2bfloat16(v.y);
    __nv_bfloat16 h2 = __float2bfloat16(v.z), h3 = __float2bfloat16(v.w);
    hv.x = pack2(h0, h1); hv.y = pack2(h2, h3);
    lv.x = pack2(__float2bfloat16(v.x - __bfloat162float(h0)),
                 __float2bfloat16(v.y - __bfloat162float(h1)));
    lv.y = pack2(__float2bfloat16(v.z - __bfloat162float(h2)),
                 __float2bfloat16(v.w - __bfloat162float(h3)));
}

// SMEM tile geometry: row = 80 B (32 bf16 data + pad), conflict-free ldmatrix
#define SROW_B   80
#define OFF_AH   0
#define OFF_AL   10240              // 128 rows * 80
#define OFF_BH   20480
#define OFF_BL   40960              // Bh is 256 rows * 80 = 20480
#define STAGE_B  61440
#define NSTAGE   3
#define SMEM_G1  (NSTAGE * STAGE_B + 512)
#define SMEM_G2  (NSTAGE * STAGE_B)

// ---------------- kernel 1: router + gate logits + x hi/lo split ------------
__global__ void router_split_kernel(const float* __restrict__ x,
                                    const float* __restrict__ gate_w,
                                    float* __restrict__ out_logits) {
    int warp = (blockIdx.x * blockDim.x + threadIdx.x) >> 5;
    int lane = threadIdx.x & 31;
    if (warp >= NTOK) return;
    const float* xp = x + (size_t)warp * DH;
    float acc[NEXP];
#pragma unroll
    for (int e = 0; e < NEXP; e++) acc[e] = 0.0f;
#pragma unroll
    for (int i = 0; i < DH / 128; i++) {           // 8 iters, 4 elems/lane
        int d = i * 128 + lane * 4;
        float4 v = *(const float4*)(xp + d);
        uint2 hv, lv; split4(v, hv, lv);
        *(uint2*)(g_X_hi + (size_t)warp * DH + d) = hv;
        *(uint2*)(g_X_lo + (size_t)warp * DH + d) = lv;
        const float* gw = gate_w + (size_t)d * NEXP;
#pragma unroll
        for (int e = 0; e < NEXP; e++)
            acc[e] += v.x * gw[e] + v.y * gw[NEXP + e]
                    + v.z * gw[2 * NEXP + e] + v.w * gw[3 * NEXP + e];
    }
#pragma unroll
    for (int e = 0; e < NEXP; e++)
#pragma unroll
        for (int o = 16; o > 0; o >>= 1)
            acc[e] += __shfl_xor_sync(0xffffffffu, acc[e], o);
    if (lane == 0) {
        if (out_logits)
#pragma unroll
            for (int e = 0; e < NEXP; e++) out_logits[warp * NEXP + e] = acc[e];
        int e0 = 0;
#pragma unroll
        for (int e = 1; e < NEXP; e++) if (acc[e] > acc[e0]) e0 = e;
        int e1 = (e0 == 0) ? 1 : 0;
#pragma unroll
        for (int e = 0; e < NEXP; e++) if (e != e0 && acc[e] > acc[e1]) e1 = e;
        float dlt = expf(acc[e1] - acc[e0]);
        float w0 = 1.0f / (1.0f + dlt);
        float w1 = dlt / (1.0f + dlt);
        g_eid[warp * 2 + 0] = e0; g_eid[warp * 2 + 1] = e1;
        g_wk [warp * 2 + 0] = w0; g_wk [warp * 2 + 1] = w1;
        atomicAdd(&g_count[e0], 1);
        atomicAdd(&g_count[e1], 1);
    }
}

// ---------------- kernel 2: fused scan + scatter (single block) --------------
__global__ void scan_scatter_kernel() {
    if (threadIdx.x == 0) {
        int acc = 0; g_off[0] = 0;
#pragma unroll
        for (int e = 0; e < NEXP; e++) { acc += g_count[e]; g_off[e + 1] = acc; }
    }
    __syncthreads();
    for (int t = threadIdx.x; t < NTOK; t += blockDim.x) {
#pragma unroll
        for (int k = 0; k < TOPK; k++) {
            int e = g_eid[t * 2 + k];
            int pos = g_off[e] + atomicAdd(&g_cursor[e], 1);
            g_tok[pos] = t;
            g_wt[pos]  = g_wk[t * 2 + k];
            g_slot[t * 2 + k] = pos;
        }
    }
}

// ------------- weight transpose + bf16 hi/lo split (vectorized stores) -------
__global__ __launch_bounds__(256)
void transpose_split_kernel(const float* __restrict__ src,
                            __nv_bfloat16* __restrict__ dh,
                            __nv_bfloat16* __restrict__ dl,
                            int K, int N) {
    __shared__ float t[32][33];
    int e = blockIdx.z;
    src += (size_t)e * K * N;
    dh  += (size_t)e * K * N;
    dl  += (size_t)e * K * N;
    int n0 = blockIdx.x * 32, k0 = blockIdx.y * 32;
    int xx = threadIdx.x, yy = threadIdx.y;  // (32, 8)
    int tid = yy * 32 + xx;
#pragma unroll
    for (int r = 0; r < 4; r++) {
        int k = yy + r * 8;
        t[k][xx] = src[(size_t)(k0 + k) * N + n0 + xx];
    }
    __syncthreads();
    // 32 n-rows x 16 k-pairs = 512 items, 256 threads, uint32 stores
#pragma unroll
    for (int it = 0; it < 2; it++) {
        int j = it * 256 + tid;
        int n = j >> 4, kp = j & 15;
        float v0 = t[2 * kp][n], v1 = t[2 * kp + 1][n];
        __nv_bfloat16 h0 = __float2bfloat16(v0), h1 = __float2bfloat16(v1);
        __nv_bfloat16 l0 = __float2bfloat16(v0 - __bfloat162float(h0));
        __nv_bfloat16 l1 = __float2bfloat16(v1 - __bfloat162float(h1));
        size_t o = (size_t)(n0 + n) * K + k0 + 2 * kp;
        *(uint32_t*)(dh + o) = pack2(h0, h1);
        *(uint32_t*)(dl + o) = pack2(l0, l1);
    }
}

// ---------------- warp-level 64x64 3-pass compute, chain-broken --------------
struct WarpAcc { float a[4][8][4]; };   // [mi][ni][frag]

__device__ __forceinline__ void compute_stage(uint32_t stb, int lane, int wm, int wn,
                                              WarpAcc& W) {
#pragma unroll
    for (int kk = 0; kk < 32; kk += 16) {
        uint32_t ah[4][4], al[4][4];
        uint32_t aoff = stb + OFF_AH
                      + (uint32_t)(wm + (lane & 15)) * SROW_B
                      + (uint32_t)(kk + ((lane >> 4) << 3)) * 2;
#pragma unroll
        for (int mi = 0; mi < 4; mi++) {
            ldsm_x4(ah[mi], aoff + mi * 16 * SROW_B);
            ldsm_x4(al[mi], aoff + mi * 16 * SROW_B + (OFF_AL - OFF_AH));
        }
        int bgrp = lane >> 3;
        uint32_t boff = stb + OFF_BH
                      + (uint32_t)(wn + (lane & 7) + ((bgrp & 2) << 2)) * SROW_B
                      + (uint32_t)(kk + ((bgrp & 1) << 3)) * 2;
#pragma unroll
        for (int p = 0; p < 4; p++) {           // ni pair (2p, 2p+1)
            uint32_t th[4], tl[4];
            ldsm_x4(th, boff + p * 16 * SROW_B);
            ldsm_x4(tl, boff + p * 16 * SROW_B + (OFF_BL - OFF_BH));
            // pass-major issue order: 8 distinct accumulators between any
            // two mma that share an accumulator (no back-to-back RAW on D)
#pragma unroll
            for (int mi = 0; mi < 4; mi++) {
                mma16816(W.a[mi][2 * p],     ah[mi], th[0], th[1]);
                mma16816(W.a[mi][2 * p + 1], ah[mi], th[2], th[3]);
            }
#pragma unroll
            for (int mi = 0; mi < 4; mi++) {
                mma16816(W.a[mi][2 * p],     ah[mi], tl[0], tl[1]);
                mma16816(W.a[mi][2 * p + 1], ah[mi], tl[2], tl[3]);
            }
#pragma unroll
            for (int mi = 0; mi < 4; mi++) {
                mma16816(W.a[mi][2 * p],     al[mi], th[0], th[1]);
                mma16816(W.a[mi][2 * p + 1], al[mi], th[2], th[3]);
            }
        }
    }
}

// ---------------- GEMM1: H = gelu(x@fc_w + b), 128x256 tile ------------------
__global__ __launch_bounds__(256, 1)
void gemm1_mma(const float* __restrict__ fc_b) {
    int e = blockIdx.z;
    int row0 = g_off[e];
    int rows = g_off[e + 1] - row0;
    int m0 = blockIdx.x * 128;
    if (m0 >= rows) return;
    int n0 = blockIdx.y * 256;

    extern __shared__ char smem[];
    uint32_t sb = smem_u32(smem);
    int tid = threadIdx.x, wid = tid >> 5, lane = tid & 31;

    int* s_tok = (int*)(smem + NSTAGE * STAGE_B);
    if (tid < 128) s_tok[tid] = (m0 + tid < rows) ? g_tok[row0 + m0 + tid] : -1;
    __syncthreads();

    const __nv_bfloat16* Bh = g_fcwT_hi + (size_t)e * FH * DH + (size_t)n0 * DH;
    const __nv_bfloat16* Bl = g_fcwT_lo + (size_t)e * FH * DH + (size_t)n0 * DH;

    const int NC = DH / 32;   // 32 stages

    auto load_stage = [&](int c) {
        uint32_t stb = sb + (c % NSTAGE) * STAGE_B;
        int kt = c * 32;
#pragma unroll
        for (int i = 0; i < 4; i++) {
            int u = tid + (i & 1) * 256;
            int row = u >> 2, ch = u & 3;
            int which = i >> 1;   // 0 hi, 1 lo
            uint32_t dst = stb + (which ? OFF_AL : OFF_AH) + row * SROW_B + ch * 16;
            int t = s_tok[row];
            const __nv_bfloat16* base = which ? g_X_lo : g_X_hi;
            const void* src = base + (size_t)(t < 0 ? 0 : t) * DH + kt + ch * 8;
            cp16(dst, src, t < 0 ? 0 : 16);
        }
#pragma unroll
        for (int i = 0; i < 8; i++) {
            int u = tid + (i & 3) * 256;
            int row = u >> 2, ch = u & 3;
            int which = i >> 2;
            uint32_t dst = stb + (which ? OFF_BL : OFF_BH) + row * SROW_B + ch * 16;
            const __nv_bfloat16* base = which ? Bl : Bh;
            const void* src = base + (size_t)row * DH + kt + ch * 8;
            cp16(dst, src, 16);
        }
    };

    WarpAcc W;
#pragma unroll
    for (int mi = 0; mi < 4; mi++)
#pragma unroll
        for (int ni = 0; ni < 8; ni++)
#pragma unroll
            for (int r = 0; r < 4; r++) W.a[mi][ni][r] = 0.0f;

    int wm = (wid & 1) * 64, wn = (wid >> 1) * 64;

    load_stage(0); CP_COMMIT();
    load_stage(1); CP_COMMIT();
    for (int c = 0; c < NC; c++) {
        CP_WAIT1();
        __syncthreads();
        if (c + 2 < NC) load_stage(c + 2);
        CP_COMMIT();
        compute_stage(sb + (c % NSTAGE) * STAGE_B, lane, wm, wn, W);
    }

    const float* bias = fc_b + (size_t)e * FH;
#pragma unroll
    for (int mi = 0; mi < 4; mi++) {
#pragma unroll
        for (int rh = 0; rh < 2; rh++) {
            int m = wm + mi * 16 + (lane >> 2) + rh * 8;
            if (m0 + m >= rows) continue;
            size_t slot = (size_t)row0 + m0 + m;
#pragma unroll
            for (int ni = 0; ni < 8; ni++) {
                int n = n0 + wn + ni * 8 + 2 * (lane & 3);
                float2 bb = *(const float2*)(bias + n);
                float v0 = gelu_new(W.a[mi][ni][2 * rh + 0] + bb.x);
                float v1 = gelu_new(W.a[mi][ni][2 * rh + 1] + bb.y);
                __nv_bfloat16 h0 = __float2bfloat16(v0), h1 = __float2bfloat16(v1);
                __nv_bfloat16 l0 = __float2bfloat16(v0 - __bfloat162float(h0));
                __nv_bfloat16 l1 = __float2bfloat16(v1 - __bfloat162float(h1));
                *(uint32_t*)(g_H_hi + slot * FH + n) = pack2(h0, h1);
                *(uint32_t*)(g_H_lo + slot * FH + n) = pack2(l0, l1);
            }
        }
    }
}

// ---------------- GEMM2: O = wt * (H@proj_w + b), 128x256 tile ---------------
__global__ __launch_bounds__(256, 1)
void gemm2_mma(const float* __restrict__ proj_b) {
    int e = blockIdx.z;
    int row0 = g_off[e];
    int rows = g_off[e + 1] - row0;
    int m0 = blockIdx.x * 128;
    if (m0 >= rows) return;
    int n0 = blockIdx.y * 256;

    extern __shared__ char smem[];
    uint32_t sb = smem_u32(smem);
    int tid = threadIdx.x, wid = tid >> 5, lane = tid & 31;

    const __nv_bfloat16* Bh = g_prjT_hi + (size_t)e * DH * FH + (size_t)n0 * FH;
    const __nv_bfloat16* Bl = g_prjT_lo + (size_t)e * DH * FH + (size_t)n0 * FH;

    const int NC = FH / 32;   // 128 stages

    auto load_stage = [&](int c) {
        uint32_t stb = sb + (c % NSTAGE) * STAGE_B;
        int kt = c * 32;
#pragma unroll
        for (int i = 0; i < 4; i++) {
            int u = tid + (i & 1) * 256;
            int row = u >> 2, ch = u & 3;
            int which = i >> 1;
            uint32_t dst = stb + (which ? OFF_AL : OFF_AH) + row * SROW_B + ch * 16;
            bool ok = (m0 + row) < rows;
            size_t slot = (size_t)row0 + m0 + (ok ? row : 0);
            const __nv_bfloat16* base = which ? g_H_lo : g_H_hi;
            const void* src = base + slot * FH + kt + ch * 8;
            cp16(dst, src, ok ? 16 : 0);
        }
#pragma unroll
        for (int i = 0; i < 8; i++) {
            int u = tid + (i & 3) * 256;
            int row = u >> 2, ch = u & 3;
            int which = i >> 2;
            uint32_t dst = stb + (which ? OFF_BL : OFF_BH) + row * SROW_B + ch * 16;
            const __nv_bfloat16* base = which ? Bl : Bh;
            const void* src = base + (size_t)row * FH + kt + ch * 8;
            cp16(dst, src, 16);
        }
    };

    WarpAcc W;
#pragma unroll
    for (int mi = 0; mi < 4; mi++)
#pragma unroll
        for (int ni = 0; ni < 8; ni++)
#pragma unroll
            for (int r = 0; r < 4; r++) W.a[mi][ni][r] = 0.0f;

    int wm = (wid & 1) * 64, wn = (wid >> 1) * 64;

    load_stage(0); CP_COMMIT();
    load_stage(1); CP_COMMIT();
    for (int c = 0; c < NC; c++) {
        CP_WAIT1();
        __syncthreads();
        if (c + 2 < NC) load_stage(c + 2);
        CP_COMMIT();
        compute_stage(sb + (c % NSTAGE) * STAGE_B, lane, wm, wn, W);
    }

    const float* bias = proj_b + (size_t)e * DH;
#pragma unroll
    for (int mi = 0; mi < 4; mi++) {
#pragma unroll
        for (int rh = 0; rh < 2; rh++) {
            int m = wm + mi * 16 + (lane >> 2) + rh * 8;
            if (m0 + m >= rows) continue;
            size_t slot = (size_t)row0 + m0 + m;
            float w = g_wt[slot];
#pragma unroll
            for (int ni = 0; ni < 8; ni++) {
                int n = n0 + wn + ni * 8 + 2 * (lane & 3);
                float2 bb = *(const float2*)(bias + n);
                float v0 = w * (W.a[mi][ni][2 * rh + 0] + bb.x);
                float v1 = w * (W.a[mi][ni][2 * rh + 1] + bb.y);
                *(float2*)(g_O + slot * DH + n) = make_float2(v0, v1);
            }
        }
    }
}

// ---------------- combine (+ counter reset for next call) --------------------
__global__ void combine_kernel(float* __restrict__ out) {
    if (blockIdx.x == 0 && threadIdx.x < NEXP) {
        g_count[threadIdx.x] = 0;
        g_cursor[threadIdx.x] = 0;
    }
    int idx = blockIdx.x * blockDim.x + threadIdx.x;
    const int DQ = DH / 4;
    if (idx >= NTOK * DQ) return;
    int t = idx / DQ;
    int dq = idx - t * DQ;
    int s0 = g_slot[t * 2 + 0];
    int s1 = g_slot[t * 2 + 1];
    const float4* o0 = (const float4*)(g_O + (size_t)s0 * DH) + dq;
    const float4* o1 = (const float4*)(g_O + (size_t)s1 * DH) + dq;
    float4 a = *o0, b = *o1;
    ((float4*)(out + (size_t)t * DH))[dq] =
        make_float4(a.x + b.x, a.y + b.y, a.z + b.z, a.w + b.w);
}

// ---------------- launch -----------------------------------------------------
extern "C" void kernel_launch(void* const* d_in, const int* in_sizes, int n_in,
                              void* d_out, int out_size) {
    const float* x      = (const float*)d_in[0];
    const float* gate_w = (const float*)d_in[1];
    const float* fc_w   = (const float*)d_in[2];
    const float* fc_b   = (const float*)d_in[3];
    const float* proj_w = (const float*)d_in[4];
    const float* proj_b = (const float*)d_in[5];

    float* out = (float*)d_out;
    float* out_logits =
        (out_size >= NTOK * DH + NTOK * NEXP) ? (out + (size_t)NTOK * DH) : nullptr;

    cudaFuncSetAttribute(gemm1_mma, cudaFuncAttributeMaxDynamicSharedMemorySize, SMEM_G1);
    cudaFuncSetAttribute(gemm2_mma, cudaFuncAttributeMaxDynamicSharedMemorySize, SMEM_G2);

    __nv_bfloat16 *fh, *fl, *ph, *pl;
    cudaGetSymbolAddress((void**)&fh, g_fcwT_hi);
    cudaGetSymbolAddress((void**)&fl, g_fcwT_lo);
    cudaGetSymbolAddress((void**)&ph, g_prjT_hi);
    cudaGetSymbolAddress((void**)&pl, g_prjT_lo);

    // ncu empirically profiles the 4th launch -> make it gemm1.
    router_split_kernel<<<NTOK / 8, 256>>>(x, gate_w, out_logits);                 // 1
    scan_scatter_kernel<<<1, 1024>>>();                                            // 2
    transpose_split_kernel<<<dim3(FH / 32, DH / 32, NEXP), dim3(32, 8)>>>(fc_w, fh, fl, DH, FH);   // 3
    gemm1_mma<<<dim3(NTOK / 128, FH / 256, NEXP), 256, SMEM_G1>>>(fc_b);           // 4  <- profiled
    transpose_split_kernel<<<dim3(DH / 32, FH / 32, NEXP), dim3(32, 8)>>>(proj_w, ph, pl, FH, DH); // 5
    gemm2_mma<<<dim3(NTOK / 128, DH / 256, NEXP), 256, SMEM_G2>>>(proj_b);         // 6
    combine_kernel<<<(NTOK * (DH / 4) + 255) / 256, 256>>>(out);                   // 7

    (void)n_in; (void)in_sizes;
}

// round 7
// speedup vs baseline: 1.0248x; 1.0248x over previous
#include <cuda_runtime.h>
#include <cuda_bf16.h>
#include <math.h>
#include <stdint.h>

// Problem constants
#define NEXP 8
#define TOPK 2
#define DH   1024
#define FH   4096
#define NTOK 4096
#define NSLOT (NTOK * TOPK)   // 8192

// ---------------- scratch (static __device__ — no allocations) -------------
__device__ __nv_bfloat16 g_X_hi[(size_t)NTOK * DH];
__device__ __nv_bfloat16 g_X_lo[(size_t)NTOK * DH];
__device__ __nv_bfloat16 g_fcwT_hi[(size_t)NEXP * FH * DH];  // [e][n(F)][k(D)]
__device__ __nv_bfloat16 g_fcwT_lo[(size_t)NEXP * FH * DH];
__device__ __nv_bfloat16 g_prjT_hi[(size_t)NEXP * DH * FH];  // [e][n(D)][k(F)]
__device__ __nv_bfloat16 g_prjT_lo[(size_t)NEXP * DH * FH];
__device__ __nv_bfloat16 g_H_hi[(size_t)NSLOT * FH];
__device__ __nv_bfloat16 g_H_lo[(size_t)NSLOT * FH];
__device__ float g_O[(size_t)NSLOT * DH];
__device__ int   g_count[NEXP];     // statically zero; re-zeroed by combine
__device__ int   g_cursor[NEXP];
__device__ int   g_off[NEXP + 1];
__device__ int   g_eid[NSLOT];
__device__ float g_wk[NSLOT];
__device__ int   g_tok[NSLOT];
__device__ float g_wt[NSLOT];
__device__ int   g_slot[NSLOT];

// ---------------- generic-PTX helpers ---------------------------------------
__device__ __forceinline__ uint32_t smem_u32(const void* p) {
    uint32_t a;
    asm("{ .reg .u64 t; cvta.to.shared.u64 t, %1; cvt.u32.u64 %0, t; }" : "=r"(a) : "l"(p));
    return a;
}
__device__ __forceinline__ void cp16(uint32_t dst, const void* src, int srcsize) {
    asm volatile("cp.async.cg.shared.global [%0], [%1], 16, %2;"
                 :: "r"(dst), "l"(src), "r"(srcsize) : "memory");
}
#define CP_COMMIT() asm volatile("cp.async.commit_group;" ::: "memory")
#define CP_WAIT1()  asm volatile("cp.async.wait_group 1;" ::: "memory")

__device__ __forceinline__ void ldsm_x4(uint32_t* r, uint32_t addr) {
    asm volatile("ldmatrix.sync.aligned.m8n8.x4.shared.b16 {%0,%1,%2,%3}, [%4];"
                 : "=r"(r[0]), "=r"(r[1]), "=r"(r[2]), "=r"(r[3]) : "r"(addr));
}
__device__ __forceinline__ void mma16816(float* d, const uint32_t* a, uint32_t b0, uint32_t b1) {
    asm volatile(
        "mma.sync.aligned.m16n8k16.row.col.f32.bf16.bf16.f32 "
        "{%0,%1,%2,%3}, {%4,%5,%6,%7}, {%8,%9}, {%0,%1,%2,%3};"
        : "+f"(d[0]), "+f"(d[1]), "+f"(d[2]), "+f"(d[3])
        : "r"(a[0]), "r"(a[1]), "r"(a[2]), "r"(a[3]), "r"(b0), "r"(b1));
}

__device__ __forceinline__ float gelu_new(float v) {
    const float c = 0.7978845608028654f;
    float u = c * (v + 0.044715f * v * v * v);
    return 0.5f * v * (1.0f + tanhf(u));
}
__device__ __forceinline__ uint32_t pack2(__nv_bfloat16 a, __nv_bfloat16 b) {
    return (uint32_t)__bfloat16_as_ushort(a) | ((uint32_t)__bfloat16_as_ushort(b) << 16);
}
__device__ __forceinline__ void split4(float4 v, uint2& hv, uint2& lv) {
    __nv_bfloat16 h0 = __float2bfloat16(v.x), h1 = __float2bfloat16(v.y);
    __nv_bfloat16 h2 = __float2bfloat16(v.z), h3 = __float2bfloat16(v.w);
    hv.x = pack2(h0, h1); hv.y = pack2(h2, h3);
    lv.x = pack2(__float2bfloat16(v.x - __bfloat162float(h0)),
                 __float2bfloat16(v.y - __bfloat162float(h1)));
    lv.y = pack2(__float2bfloat16(v.z - __bfloat162float(h2)),
                 __float2bfloat16(v.w - __bfloat162float(h3)));
}

// SMEM tile geometry: row = 80 B (32 bf16 data + pad), conflict-free ldmatrix
#define SROW_B   80
#define OFF_AH   0
#define OFF_AL   10240              // 128 rows * 80
#define OFF_BH   20480
#define OFF_BL   40960              // Bh is 256 rows * 80 = 20480
#define STAGE_B  61440
#define NSTAGE   3
#define SMEM_G1  (NSTAGE * STAGE_B + 512)
#define SMEM_G2  (NSTAGE * STAGE_B)
#define BLOCK    512

// ---------------- kernel 1: router + gate logits + x hi/lo split ------------
__global__ void router_split_kernel(const float* __restrict__ x,
                                    const float* __restrict__ gate_w,
                                    float* __restrict__ out_logits) {
    int warp = (blockIdx.x * blockDim.x + threadIdx.x) >> 5;
    int lane = threadIdx.x & 31;
    if (warp >= NTOK) return;
    const float* xp = x + (size_t)warp * DH;
    float acc[NEXP];
#pragma unroll
    for (int e = 0; e < NEXP; e++) acc[e] = 0.0f;
#pragma unroll
    for (int i = 0; i < DH / 128; i++) {
        int d = i * 128 + lane * 4;
        float4 v = *(const float4*)(xp + d);
        uint2 hv, lv; split4(v, hv, lv);
        *(uint2*)(g_X_hi + (size_t)warp * DH + d) = hv;
        *(uint2*)(g_X_lo + (size_t)warp * DH + d) = lv;
        const float* gw = gate_w + (size_t)d * NEXP;
#pragma unroll
        for (int e = 0; e < NEXP; e++)
            acc[e] += v.x * gw[e] + v.y * gw[NEXP + e]
                    + v.z * gw[2 * NEXP + e] + v.w * gw[3 * NEXP + e];
    }
#pragma unroll
    for (int e = 0; e < NEXP; e++)
#pragma unroll
        for (int o = 16; o > 0; o >>= 1)
            acc[e] += __shfl_xor_sync(0xffffffffu, acc[e], o);
    if (lane == 0) {
        if (out_logits)
#pragma unroll
            for (int e = 0; e < NEXP; e++) out_logits[warp * NEXP + e] = acc[e];
        int e0 = 0;
#pragma unroll
        for (int e = 1; e < NEXP; e++) if (acc[e] > acc[e0]) e0 = e;
        int e1 = (e0 == 0) ? 1 : 0;
#pragma unroll
        for (int e = 0; e < NEXP; e++) if (e != e0 && acc[e] > acc[e1]) e1 = e;
        float dlt = expf(acc[e1] - acc[e0]);
        float w0 = 1.0f / (1.0f + dlt);
        float w1 = dlt / (1.0f + dlt);
        g_eid[warp * 2 + 0] = e0; g_eid[warp * 2 + 1] = e1;
        g_wk [warp * 2 + 0] = w0; g_wk [warp * 2 + 1] = w1;
        atomicAdd(&g_count[e0], 1);
        atomicAdd(&g_count[e1], 1);
    }
}

// ---------------- kernel 2: fused scan + scatter (single block) --------------
__global__ void scan_scatter_kernel() {
    if (threadIdx.x == 0) {
        int acc = 0; g_off[0] = 0;
#pragma unroll
        for (int e = 0; e < NEXP; e++) { acc += g_count[e]; g_off[e + 1] = acc; }
    }
    __syncthreads();
    for (int t = threadIdx.x; t < NTOK; t += blockDim.x) {
#pragma unroll
        for (int k = 0; k < TOPK; k++) {
            int e = g_eid[t * 2 + k];
            int pos = g_off[e] + atomicAdd(&g_cursor[e], 1);
            g_tok[pos] = t;
            g_wt[pos]  = g_wk[t * 2 + k];
            g_slot[t * 2 + k] = pos;
        }
    }
}

// ------------- weight transpose + bf16 hi/lo split (vectorized stores) -------
__global__ __launch_bounds__(256)
void transpose_split_kernel(const float* __restrict__ src,
                            __nv_bfloat16* __restrict__ dh,
                            __nv_bfloat16* __restrict__ dl,
                            int K, int N) {
    __shared__ float t[32][33];
    int e = blockIdx.z;
    src += (size_t)e * K * N;
    dh  += (size_t)e * K * N;
    dl  += (size_t)e * K * N;
    int n0 = blockIdx.x * 32, k0 = blockIdx.y * 32;
    int xx = threadIdx.x, yy = threadIdx.y;  // (32, 8)
    int tid = yy * 32 + xx;
#pragma unroll
    for (int r = 0; r < 4; r++) {
        int k = yy + r * 8;
        t[k][xx] = src[(size_t)(k0 + k) * N + n0 + xx];
    }
    __syncthreads();
#pragma unroll
    for (int it = 0; it < 2; it++) {
        int j = it * 256 + tid;
        int n = j >> 4, kp = j & 15;
        float v0 = t[2 * kp][n], v1 = t[2 * kp + 1][n];
        __nv_bfloat16 h0 = __float2bfloat16(v0), h1 = __float2bfloat16(v1);
        __nv_bfloat16 l0 = __float2bfloat16(v0 - __bfloat162float(h0));
        __nv_bfloat16 l1 = __float2bfloat16(v1 - __bfloat162float(h1));
        size_t o = (size_t)(n0 + n) * K + k0 + 2 * kp;
        *(uint32_t*)(dh + o) = pack2(h0, h1);
        *(uint32_t*)(dl + o) = pack2(l0, l1);
    }
}

// ---------------- warp-level 64x32 3-pass compute over one 32-wide stage ----
struct WarpAcc { float a[4][4][4]; };   // [mi][nfrag][frag]

__device__ __forceinline__ void compute_stage(uint32_t stb, int lane, int wm, int wn,
                                              WarpAcc& W) {
#pragma unroll
    for (int kk = 0; kk < 32; kk += 16) {
        uint32_t ah[4][4], al[4][4];
        uint32_t aoff = stb + OFF_AH
                      + (uint32_t)(wm + (lane & 15)) * SROW_B
                      + (uint32_t)(kk + ((lane >> 4) << 3)) * 2;
#pragma unroll
        for (int mi = 0; mi < 4; mi++) {
            ldsm_x4(ah[mi], aoff + mi * 16 * SROW_B);
            ldsm_x4(al[mi], aoff + mi * 16 * SROW_B + (OFF_AL - OFF_AH));
        }
        int bgrp = lane >> 3;
        uint32_t boff = stb + OFF_BH
                      + (uint32_t)(wn + (lane & 7) + ((bgrp & 2) << 2)) * SROW_B
                      + (uint32_t)(kk + ((bgrp & 1) << 3)) * 2;
#pragma unroll
        for (int p = 0; p < 2; p++) {           // n-frag pair (2p, 2p+1)
            uint32_t th[4], tl[4];
            ldsm_x4(th, boff + p * 16 * SROW_B);
            ldsm_x4(tl, boff + p * 16 * SROW_B + (OFF_BL - OFF_BH));
#pragma unroll
            for (int mi = 0; mi < 4; mi++) {
                mma16816(W.a[mi][2 * p],     ah[mi], th[0], th[1]);
                mma16816(W.a[mi][2 * p + 1], ah[mi], th[2], th[3]);
            }
#pragma unroll
            for (int mi = 0; mi < 4; mi++) {
                mma16816(W.a[mi][2 * p],     ah[mi], tl[0], tl[1]);
                mma16816(W.a[mi][2 * p + 1], ah[mi], tl[2], tl[3]);
            }
#pragma unroll
            for (int mi = 0; mi < 4; mi++) {
                mma16816(W.a[mi][2 * p],     al[mi], th[0], th[1]);
                mma16816(W.a[mi][2 * p + 1], al[mi], th[2], th[3]);
            }
        }
    }
}

// ---------------- GEMM1: H = gelu(x@fc_w + b), 128x256 tile, 512 thr --------
__global__ __launch_bounds__(BLOCK, 1)
void gemm1_mma(const float* __restrict__ fc_b) {
    int e = blockIdx.z;
    int row0 = g_off[e];
    int rows = g_off[e + 1] - row0;
    int m0 = blockIdx.x * 128;
    if (m0 >= rows) return;
    int n0 = blockIdx.y * 256;

    extern __shared__ char smem[];
    uint32_t sb = smem_u32(smem);
    int tid = threadIdx.x, wid = tid >> 5, lane = tid & 31;

    int* s_tok = (int*)(smem + NSTAGE * STAGE_B);
    if (tid < 128) s_tok[tid] = (m0 + tid < rows) ? g_tok[row0 + m0 + tid] : -1;
    __syncthreads();

    const __nv_bfloat16* Bh = g_fcwT_hi + (size_t)e * FH * DH + (size_t)n0 * DH;
    const __nv_bfloat16* Bl = g_fcwT_lo + (size_t)e * FH * DH + (size_t)n0 * DH;

    const int NC = DH / 32;   // 32 stages

    auto load_stage = [&](int c) {
        uint32_t stb = sb + (c % NSTAGE) * STAGE_B;
        int kt = c * 32;
        int row = tid >> 2, ch = tid & 3;   // A quarters: 512 items each
        {
            int t = s_tok[row];
            const void* sh = g_X_hi + (size_t)(t < 0 ? 0 : t) * DH + kt + ch * 8;
            const void* sl = g_X_lo + (size_t)(t < 0 ? 0 : t) * DH + kt + ch * 8;
            uint32_t d0 = stb + OFF_AH + row * SROW_B + ch * 16;
            cp16(d0, sh, t < 0 ? 0 : 16);
            cp16(d0 + (OFF_AL - OFF_AH), sl, t < 0 ? 0 : 16);
        }
#pragma unroll
        for (int i = 0; i < 4; i++) {       // B quarters: 1024 items each
            int u = tid + (i & 1) * BLOCK;
            int br = u >> 2, bc = u & 3;
            int which = i >> 1;
            uint32_t dst = stb + (which ? OFF_BL : OFF_BH) + br * SROW_B + bc * 16;
            const __nv_bfloat16* base = which ? Bl : Bh;
            cp16(dst, base + (size_t)br * DH + kt + bc * 8, 16);
        }
    };

    WarpAcc W;
#pragma unroll
    for (int mi = 0; mi < 4; mi++)
#pragma unroll
        for (int ni = 0; ni < 4; ni++)
#pragma unroll
            for (int r = 0; r < 4; r++) W.a[mi][ni][r] = 0.0f;

    int wm = (wid & 1) * 64, wn = (wid >> 1) * 32;

    load_stage(0); CP_COMMIT();
    load_stage(1); CP_COMMIT();
    for (int c = 0; c < NC; c++) {
        CP_WAIT1();
        __syncthreads();
        if (c + 2 < NC) load_stage(c + 2);
        CP_COMMIT();
        compute_stage(sb + (c % NSTAGE) * STAGE_B, lane, wm, wn, W);
    }

    const float* bias = fc_b + (size_t)e * FH;
#pragma unroll
    for (int mi = 0; mi < 4; mi++) {
#pragma unroll
        for (int rh = 0; rh < 2; rh++) {
            int m = wm + mi * 16 + (lane >> 2) + rh * 8;
            if (m0 + m >= rows) continue;
            size_t slot = (size_t)row0 + m0 + m;
#pragma unroll
            for (int ni = 0; ni < 4; ni++) {
                int n = n0 + wn + ni * 8 + 2 * (lane & 3);
                float2 bb = *(const float2*)(bias + n);
                float v0 = gelu_new(W.a[mi][ni][2 * rh + 0] + bb.x);
                float v1 = gelu_new(W.a[mi][ni][2 * rh + 1] + bb.y);
                __nv_bfloat16 h0 = __float2bfloat16(v0), h1 = __float2bfloat16(v1);
                __nv_bfloat16 l0 = __float2bfloat16(v0 - __bfloat162float(h0));
                __nv_bfloat16 l1 = __float2bfloat16(v1 - __bfloat162float(h1));
                *(uint32_t*)(g_H_hi + slot * FH + n) = pack2(h0, h1);
                *(uint32_t*)(g_H_lo + slot * FH + n) = pack2(l0, l1);
            }
        }
    }
}

// ---------------- GEMM2: O = wt * (H@proj_w + b), 128x256 tile, 512 thr -----
__global__ __launch_bounds__(BLOCK, 1)
void gemm2_mma(const float* __restrict__ proj_b) {
    int e = blockIdx.z;
    int row0 = g_off[e];
    int rows = g_off[e + 1] - row0;
    int m0 = blockIdx.x * 128;
    if (m0 >= rows) return;
    int n0 = blockIdx.y * 256;

    extern __shared__ char smem[];
    uint32_t sb = smem_u32(smem);
    int tid = threadIdx.x, wid = tid >> 5, lane = tid & 31;

    const __nv_bfloat16* Bh = g_prjT_hi + (size_t)e * DH * FH + (size_t)n0 * FH;
    const __nv_bfloat16* Bl = g_prjT_lo + (size_t)e * DH * FH + (size_t)n0 * FH;

    const int NC = FH / 32;   // 128 stages

    auto load_stage = [&](int c) {
        uint32_t stb = sb + (c % NSTAGE) * STAGE_B;
        int kt = c * 32;
        int row = tid >> 2, ch = tid & 3;
        {
            bool ok = (m0 + row) < rows;
            size_t slot = (size_t)row0 + m0 + (ok ? row : 0);
            uint32_t d0 = stb + OFF_AH + row * SROW_B + ch * 16;
            cp16(d0, g_H_hi + slot * FH + kt + ch * 8, ok ? 16 : 0);
            cp16(d0 + (OFF_AL - OFF_AH), g_H_lo + slot * FH + kt + ch * 8, ok ? 16 : 0);
        }
#pragma unroll
        for (int i = 0; i < 4; i++) {
            int u = tid + (i & 1) * BLOCK;
            int br = u >> 2, bc = u & 3;
            int which = i >> 1;
            uint32_t dst = stb + (which ? OFF_BL : OFF_BH) + br * SROW_B + bc * 16;
            const __nv_bfloat16* base = which ? Bl : Bh;
            cp16(dst, base + (size_t)br * FH + kt + bc * 8, 16);
        }
    };

    WarpAcc W;
#pragma unroll
    for (int mi = 0; mi < 4; mi++)
#pragma unroll
        for (int ni = 0; ni < 4; ni++)
#pragma unroll
            for (int r = 0; r < 4; r++) W.a[mi][ni][r] = 0.0f;

    int wm = (wid & 1) * 64, wn = (wid >> 1) * 32;

    load_stage(0); CP_COMMIT();
    load_stage(1); CP_COMMIT();
    for (int c = 0; c < NC; c++) {
        CP_WAIT1();
        __syncthreads();
        if (c + 2 < NC) load_stage(c + 2);
        CP_COMMIT();
        compute_stage(sb + (c % NSTAGE) * STAGE_B, lane, wm, wn, W);
    }

    const float* bias = proj_b + (size_t)e * DH;
#pragma unroll
    for (int mi = 0; mi < 4; mi++) {
#pragma unroll
        for (int rh = 0; rh < 2; rh++) {
            int m = wm + mi * 16 + (lane >> 2) + rh * 8;
            if (m0 + m >= rows) continue;
            size_t slot = (size_t)row0 + m0 + m;
            float w = g_wt[slot];
#pragma unroll
            for (int ni = 0; ni < 4; ni++) {
                int n = n0 + wn + ni * 8 + 2 * (lane & 3);
                float2 bb = *(const float2*)(bias + n);
                float v0 = w * (W.a[mi][ni][2 * rh + 0] + bb.x);
                float v1 = w * (W.a[mi][ni][2 * rh + 1] + bb.y);
                *(float2*)(g_O + slot * DH + n) = make_float2(v0, v1);
            }
        }
    }
}

// ---------------- combine (+ counter reset for next call) --------------------
__global__ void combine_kernel(float* __restrict__ out) {
    if (blockIdx.x == 0 && threadIdx.x < NEXP) {
        g_count[threadIdx.x] = 0;
        g_cursor[threadIdx.x] = 0;
    }
    int idx = blockIdx.x * blockDim.x + threadIdx.x;
    const int DQ = DH / 4;
    if (idx >= NTOK * DQ) return;
    int t = idx / DQ;
    int dq = idx - t * DQ;
    int s0 = g_slot[t * 2 + 0];
    int s1 = g_slot[t * 2 + 1];
    const float4* o0 = (const float4*)(g_O + (size_t)s0 * DH) + dq;
    const float4* o1 = (const float4*)(g_O + (size_t)s1 * DH) + dq;
    float4 a = *o0, b = *o1;
    ((float4*)(out + (size_t)t * DH))[dq] =
        make_float4(a.x + b.x, a.y + b.y, a.z + b.z, a.w + b.w);
}

// ---------------- launch -----------------------------------------------------
extern "C" void kernel_launch(void* const* d_in, const int* in_sizes, int n_in,
                              void* d_out, int out_size) {
    const float* x      = (const float*)d_in[0];
    const float* gate_w = (const float*)d_in[1];
    const float* fc_w   = (const float*)d_in[2];
    const float* fc_b   = (const float*)d_in[3];
    const float* proj_w = (const float*)d_in[4];
    const float* proj_b = (const float*)d_in[5];

    float* out = (float*)d_out;
    float* out_logits =
        (out_size >= NTOK * DH + NTOK * NEXP) ? (out + (size_t)NTOK * DH) : nullptr;

    cudaFuncSetAttribute(gemm1_mma, cudaFuncAttributeMaxDynamicSharedMemorySize, SMEM_G1);
    cudaFuncSetAttribute(gemm2_mma, cudaFuncAttributeMaxDynamicSharedMemorySize, SMEM_G2);

    __nv_bfloat16 *fh, *fl, *ph, *pl;
    cudaGetSymbolAddress((void**)&fh, g_fcwT_hi);
    cudaGetSymbolAddress((void**)&fl, g_fcwT_lo);
    cudaGetSymbolAddress((void**)&ph, g_prjT_hi);
    cudaGetSymbolAddress((void**)&pl, g_prjT_lo);

    // ncu profiles the 4th launch -> keep it gemm1.
    router_split_kernel<<<NTOK / 8, 256>>>(x, gate_w, out_logits);                 // 1
    scan_scatter_kernel<<<1, 1024>>>();                                            // 2
    transpose_split_kernel<<<dim3(FH / 32, DH / 32, NEXP), dim3(32, 8)>>>(fc_w, fh, fl, DH, FH);   // 3
    gemm1_mma<<<dim3(NTOK / 128, FH / 256, NEXP), BLOCK, SMEM_G1>>>(fc_b);         // 4  <- profiled
    transpose_split_kernel<<<dim3(DH / 32, FH / 32, NEXP), dim3(32, 8)>>>(proj_w, ph, pl, FH, DH); // 5
    gemm2_mma<<<dim3(NTOK / 128, DH / 256, NEXP), BLOCK, SMEM_G2>>>(proj_b);       // 6
    combine_kernel<<<(NTOK * (DH / 4) + 255) / 256, 256>>>(out);                   // 7

    (void)n_in; (void)in_sizes;
}

// round 8
// speedup vs baseline: 1.1213x; 1.0942x over previous
#include <cuda_runtime.h>
#include <cuda_bf16.h>
#include <math.h>
#include <stdint.h>

// Problem constants
#define NEXP 8
#define TOPK 2
#define DH   1024
#define FH   4096
#define NTOK 4096
#define NSLOT (NTOK * TOPK)   // 8192

// ---------------- scratch (static __device__ — no allocations) -------------
__device__ __nv_bfloat16 g_X_hi[(size_t)NTOK * DH];
__device__ __nv_bfloat16 g_X_lo[(size_t)NTOK * DH];
__device__ __nv_bfloat16 g_fcwT_hi[(size_t)NEXP * FH * DH];  // [e][n(F)][k(D)]
__device__ __nv_bfloat16 g_fcwT_lo[(size_t)NEXP * FH * DH];
__device__ __nv_bfloat16 g_prjT_hi[(size_t)NEXP * DH * FH];  // [e][n(D)][k(F)]
__device__ __nv_bfloat16 g_prjT_lo[(size_t)NEXP * DH * FH];
__device__ __nv_bfloat16 g_H_hi[(size_t)NSLOT * FH];
__device__ __nv_bfloat16 g_H_lo[(size_t)NSLOT * FH];
__device__ float g_O[(size_t)NSLOT * DH];
__device__ int   g_count[NEXP];     // statically zero; re-zeroed by combine
__device__ int   g_cursor[NEXP];
__device__ int   g_off[NEXP + 1];
__device__ int   g_eid[NSLOT];
__device__ float g_wk[NSLOT];
__device__ int   g_tok[NSLOT];
__device__ float g_wt[NSLOT];
__device__ int   g_slot[NSLOT];

// ---------------- generic-PTX helpers ---------------------------------------
__device__ __forceinline__ uint32_t smem_u32(const void* p) {
    uint32_t a;
    asm("{ .reg .u64 t; cvta.to.shared.u64 t, %1; cvt.u32.u64 %0, t; }" : "=r"(a) : "l"(p));
    return a;
}
__device__ __forceinline__ void cp16(uint32_t dst, const void* src, int srcsize) {
    asm volatile("cp.async.cg.shared.global [%0], [%1], 16, %2;"
                 :: "r"(dst), "l"(src), "r"(srcsize) : "memory");
}
#define CP_COMMIT() asm volatile("cp.async.commit_group;" ::: "memory")
#define CP_WAIT0()  asm volatile("cp.async.wait_group 0;" ::: "memory")

__device__ __forceinline__ void ldsm_x4(uint32_t* r, uint32_t addr) {
    asm volatile("ldmatrix.sync.aligned.m8n8.x4.shared.b16 {%0,%1,%2,%3}, [%4];"
                 : "=r"(r[0]), "=r"(r[1]), "=r"(r[2]), "=r"(r[3]) : "r"(addr));
}
__device__ __forceinline__ void mma16816(float* d, const uint32_t* a, uint32_t b0, uint32_t b1) {
    asm volatile(
        "mma.sync.aligned.m16n8k16.row.col.f32.bf16.bf16.f32 "
        "{%0,%1,%2,%3}, {%4,%5,%6,%7}, {%8,%9}, {%0,%1,%2,%3};"
        : "+f"(d[0]), "+f"(d[1]), "+f"(d[2]), "+f"(d[3])
        : "r"(a[0]), "r"(a[1]), "r"(a[2]), "r"(a[3]), "r"(b0), "r"(b1));
}

__device__ __forceinline__ float gelu_new(float v) {
    const float c = 0.7978845608028654f;
    float u = c * (v + 0.044715f * v * v * v);
    return 0.5f * v * (1.0f + tanhf(u));
}
__device__ __forceinline__ uint32_t pack2(__nv_bfloat16 a, __nv_bfloat16 b) {
    return (uint32_t)__bfloat16_as_ushort(a) | ((uint32_t)__bfloat16_as_ushort(b) << 16);
}
__device__ __forceinline__ void split4(float4 v, uint2& hv, uint2& lv) {
    __nv_bfloat16 h0 = __float2bfloat16(v.x), h1 = __float2bfloat16(v.y);
    __nv_bfloat16 h2 = __float2bfloat16(v.z), h3 = __float2bfloat16(v.w);
    hv.x = pack2(h0, h1); hv.y = pack2(h2, h3);
    lv.x = pack2(__float2bfloat16(v.x - __bfloat162float(h0)),
                 __float2bfloat16(v.y - __bfloat162float(h1)));
    lv.y = pack2(__float2bfloat16(v.z - __bfloat162float(h2)),
                 __float2bfloat16(v.w - __bfloat162float(h3)));
}

// SMEM tile geometry: K-stage = 64, row = 144 B (128 B data + 16 B pad)
#define SROW_B   144
#define OFF_AH   0
#define OFF_AL   18432              // 128 rows * 144
#define OFF_BH   36864
#define OFF_BL   73728              // Bh is 256 rows * 144 = 36864
#define STAGE_B  110592             // 36864 + 73728
#define NSTAGE   2
#define SMEM_G1  (NSTAGE * STAGE_B + 512)   // 221696
#define SMEM_G2  (NSTAGE * STAGE_B)
#define BLOCK    512

// ---------------- kernel 1: router + gate logits + x hi/lo split ------------
__global__ void router_split_kernel(const float* __restrict__ x,
                                    const float* __restrict__ gate_w,
                                    float* __restrict__ out_logits) {
    int warp = (blockIdx.x * blockDim.x + threadIdx.x) >> 5;
    int lane = threadIdx.x & 31;
    if (warp >= NTOK) return;
    const float* xp = x + (size_t)warp * DH;
    float acc[NEXP];
#pragma unroll
    for (int e = 0; e < NEXP; e++) acc[e] = 0.0f;
#pragma unroll
    for (int i = 0; i < DH / 128; i++) {
        int d = i * 128 + lane * 4;
        float4 v = *(const float4*)(xp + d);
        uint2 hv, lv; split4(v, hv, lv);
        *(uint2*)(g_X_hi + (size_t)warp * DH + d) = hv;
        *(uint2*)(g_X_lo + (size_t)warp * DH + d) = lv;
        const float* gw = gate_w + (size_t)d * NEXP;
#pragma unroll
        for (int e = 0; e < NEXP; e++)
            acc[e] += v.x * gw[e] + v.y * gw[NEXP + e]
                    + v.z * gw[2 * NEXP + e] + v.w * gw[3 * NEXP + e];
    }
#pragma unroll
    for (int e = 0; e < NEXP; e++)
#pragma unroll
        for (int o = 16; o > 0; o >>= 1)
            acc[e] += __shfl_xor_sync(0xffffffffu, acc[e], o);
    if (lane == 0) {
        if (out_logits)
#pragma unroll
            for (int e = 0; e < NEXP; e++) out_logits[warp * NEXP + e] = acc[e];
        int e0 = 0;
#pragma unroll
        for (int e = 1; e < NEXP; e++) if (acc[e] > acc[e0]) e0 = e;
        int e1 = (e0 == 0) ? 1 : 0;
#pragma unroll
        for (int e = 0; e < NEXP; e++) if (e != e0 && acc[e] > acc[e1]) e1 = e;
        float dlt = expf(acc[e1] - acc[e0]);
        float w0 = 1.0f / (1.0f + dlt);
        float w1 = dlt / (1.0f + dlt);
        g_eid[warp * 2 + 0] = e0; g_eid[warp * 2 + 1] = e1;
        g_wk [warp * 2 + 0] = w0; g_wk [warp * 2 + 1] = w1;
        atomicAdd(&g_count[e0], 1);
        atomicAdd(&g_count[e1], 1);
    }
}

// ---------------- kernel 2: fused scan + scatter (single block) --------------
__global__ void scan_scatter_kernel() {
    if (threadIdx.x == 0) {
        int acc = 0; g_off[0] = 0;
#pragma unroll
        for (int e = 0; e < NEXP; e++) { acc += g_count[e]; g_off[e + 1] = acc; }
    }
    __syncthreads();
    for (int t = threadIdx.x; t < NTOK; t += blockDim.x) {
#pragma unroll
        for (int k = 0; k < TOPK; k++) {
            int e = g_eid[t * 2 + k];
            int pos = g_off[e] + atomicAdd(&g_cursor[e], 1);
            g_tok[pos] = t;
            g_wt[pos]  = g_wk[t * 2 + k];
            g_slot[t * 2 + k] = pos;
        }
    }
}

// ------------- weight transpose + bf16 hi/lo split (vectorized stores) -------
__global__ __launch_bounds__(256)
void transpose_split_kernel(const float* __restrict__ src,
                            __nv_bfloat16* __restrict__ dh,
                            __nv_bfloat16* __restrict__ dl,
                            int K, int N) {
    __shared__ float t[32][33];
    int e = blockIdx.z;
    src += (size_t)e * K * N;
    dh  += (size_t)e * K * N;
    dl  += (size_t)e * K * N;
    int n0 = blockIdx.x * 32, k0 = blockIdx.y * 32;
    int xx = threadIdx.x, yy = threadIdx.y;  // (32, 8)
    int tid = yy * 32 + xx;
#pragma unroll
    for (int r = 0; r < 4; r++) {
        int k = yy + r * 8;
        t[k][xx] = src[(size_t)(k0 + k) * N + n0 + xx];
    }
    __syncthreads();
#pragma unroll
    for (int it = 0; it < 2; it++) {
        int j = it * 256 + tid;
        int n = j >> 4, kp = j & 15;
        float v0 = t[2 * kp][n], v1 = t[2 * kp + 1][n];
        __nv_bfloat16 h0 = __float2bfloat16(v0), h1 = __float2bfloat16(v1);
        __nv_bfloat16 l0 = __float2bfloat16(v0 - __bfloat162float(h0));
        __nv_bfloat16 l1 = __float2bfloat16(v1 - __bfloat162float(h1));
        size_t o = (size_t)(n0 + n) * K + k0 + 2 * kp;
        *(uint32_t*)(dh + o) = pack2(h0, h1);
        *(uint32_t*)(dl + o) = pack2(l0, l1);
    }
}

// ---------------- warp-level 64x32 3-pass compute over one 64-wide stage ----
struct WarpAcc { float a[4][4][4]; };   // [mi][nfrag][frag]

__device__ __forceinline__ void compute_stage(uint32_t stb, int lane, int wm, int wn,
                                              WarpAcc& W) {
#pragma unroll
    for (int kk = 0; kk < 64; kk += 16) {
        uint32_t ah[4][4], al[4][4];
        uint32_t aoff = stb + OFF_AH
                      + (uint32_t)(wm + (lane & 15)) * SROW_B
                      + (uint32_t)(kk + ((lane >> 4) << 3)) * 2;
#pragma unroll
        for (int mi = 0; mi < 4; mi++) {
            ldsm_x4(ah[mi], aoff + mi * 16 * SROW_B);
            ldsm_x4(al[mi], aoff + mi * 16 * SROW_B + (OFF_AL - OFF_AH));
        }
        int bgrp = lane >> 3;
        uint32_t boff = stb + OFF_BH
                      + (uint32_t)(wn + (lane & 7) + ((bgrp & 2) << 2)) * SROW_B
                      + (uint32_t)(kk + ((bgrp & 1) << 3)) * 2;
#pragma unroll
        for (int p = 0; p < 2; p++) {           // n-frag pair (2p, 2p+1)
            uint32_t th[4], tl[4];
            ldsm_x4(th, boff + p * 16 * SROW_B);
            ldsm_x4(tl, boff + p * 16 * SROW_B + (OFF_BL - OFF_BH));
#pragma unroll
            for (int mi = 0; mi < 4; mi++) {
                mma16816(W.a[mi][2 * p],     ah[mi], th[0], th[1]);
                mma16816(W.a[mi][2 * p + 1], ah[mi], th[2], th[3]);
            }
#pragma unroll
            for (int mi = 0; mi < 4; mi++) {
                mma16816(W.a[mi][2 * p],     ah[mi], tl[0], tl[1]);
                mma16816(W.a[mi][2 * p + 1], ah[mi], tl[2], tl[3]);
            }
#pragma unroll
            for (int mi = 0; mi < 4; mi++) {
                mma16816(W.a[mi][2 * p],     al[mi], th[0], th[1]);
                mma16816(W.a[mi][2 * p + 1], al[mi], th[2], th[3]);
            }
        }
    }
}

// ---------------- GEMM1: H = gelu(x@fc_w + b), 128x256 tile, KC=64 ----------
__global__ __launch_bounds__(BLOCK, 1)
void gemm1_mma(const float* __restrict__ fc_b) {
    int e = blockIdx.z;
    int row0 = g_off[e];
    int rows = g_off[e + 1] - row0;
    int m0 = blockIdx.x * 128;
    if (m0 >= rows) return;
    int n0 = blockIdx.y * 256;

    extern __shared__ char smem[];
    uint32_t sb = smem_u32(smem);
    int tid = threadIdx.x, wid = tid >> 5, lane = tid & 31;

    int* s_tok = (int*)(smem + NSTAGE * STAGE_B);
    if (tid < 128) s_tok[tid] = (m0 + tid < rows) ? g_tok[row0 + m0 + tid] : -1;
    __syncthreads();

    const __nv_bfloat16* Bh = g_fcwT_hi + (size_t)e * FH * DH + (size_t)n0 * DH;
    const __nv_bfloat16* Bl = g_fcwT_lo + (size_t)e * FH * DH + (size_t)n0 * DH;

    const int NC = DH / 64;   // 16 stages

    auto load_stage = [&](int c) {
        uint32_t stb = sb + (c & 1) * STAGE_B;
        int kt = c * 64;
        // A: 128 rows x 8 chunks, hi & lo (1024 sites each)
#pragma unroll
        for (int i = 0; i < 4; i++) {
            int u = tid + (i & 1) * BLOCK;
            int row = u >> 3, ch = u & 7;
            int which = i >> 1;   // 0 hi, 1 lo
            uint32_t dst = stb + (which ? OFF_AL : OFF_AH) + row * SROW_B + ch * 16;
            int t = s_tok[row];
            const __nv_bfloat16* base = which ? g_X_lo : g_X_hi;
            cp16(dst, base + (size_t)(t < 0 ? 0 : t) * DH + kt + ch * 8, t < 0 ? 0 : 16);
        }
        // B: 256 rows x 8 chunks, hi & lo (2048 sites each)
#pragma unroll
        for (int i = 0; i < 8; i++) {
            int u = tid + (i & 3) * BLOCK;
            int row = u >> 3, ch = u & 7;
            int which = i >> 2;
            uint32_t dst = stb + (which ? OFF_BL : OFF_BH) + row * SROW_B + ch * 16;
            const __nv_bfloat16* base = which ? Bl : Bh;
            cp16(dst, base + (size_t)row * DH + kt + ch * 8, 16);
        }
    };

    WarpAcc W;
#pragma unroll
    for (int mi = 0; mi < 4; mi++)
#pragma unroll
        for (int ni = 0; ni < 4; ni++)
#pragma unroll
            for (int r = 0; r < 4; r++) W.a[mi][ni][r] = 0.0f;

    int wm = (wid & 1) * 64, wn = (wid >> 1) * 32;

    load_stage(0); CP_COMMIT();
    for (int c = 0; c < NC; c++) {
        CP_WAIT0();
        __syncthreads();
        if (c + 1 < NC) load_stage(c + 1);
        CP_COMMIT();
        compute_stage(sb + (c & 1) * STAGE_B, lane, wm, wn, W);
    }

    const float* bias = fc_b + (size_t)e * FH;
#pragma unroll
    for (int mi = 0; mi < 4; mi++) {
#pragma unroll
        for (int rh = 0; rh < 2; rh++) {
            int m = wm + mi * 16 + (lane >> 2) + rh * 8;
            if (m0 + m >= rows) continue;
            size_t slot = (size_t)row0 + m0 + m;
#pragma unroll
            for (int ni = 0; ni < 4; ni++) {
                int n = n0 + wn + ni * 8 + 2 * (lane & 3);
                float2 bb = *(const float2*)(bias + n);
                float v0 = gelu_new(W.a[mi][ni][2 * rh + 0] + bb.x);
                float v1 = gelu_new(W.a[mi][ni][2 * rh + 1] + bb.y);
                __nv_bfloat16 h0 = __float2bfloat16(v0), h1 = __float2bfloat16(v1);
                __nv_bfloat16 l0 = __float2bfloat16(v0 - __bfloat162float(h0));
                __nv_bfloat16 l1 = __float2bfloat16(v1 - __bfloat162float(h1));
                *(uint32_t*)(g_H_hi + slot * FH + n) = pack2(h0, h1);
                *(uint32_t*)(g_H_lo + slot * FH + n) = pack2(l0, l1);
            }
        }
    }
}

// ---------------- GEMM2: O = wt * (H@proj_w + b), 128x256 tile, KC=64 -------
__global__ __launch_bounds__(BLOCK, 1)
void gemm2_mma(const float* __restrict__ proj_b) {
    int e = blockIdx.z;
    int row0 = g_off[e];
    int rows = g_off[e + 1] - row0;
    int m0 = blockIdx.x * 128;
    if (m0 >= rows) return;
    int n0 = blockIdx.y * 256;

    extern __shared__ char smem[];
    uint32_t sb = smem_u32(smem);
    int tid = threadIdx.x, wid = tid >> 5, lane = tid & 31;

    const __nv_bfloat16* Bh = g_prjT_hi + (size_t)e * DH * FH + (size_t)n0 * FH;
    const __nv_bfloat16* Bl = g_prjT_lo + (size_t)e * DH * FH + (size_t)n0 * FH;

    const int NC = FH / 64;   // 64 stages

    auto load_stage = [&](int c) {
        uint32_t stb = sb + (c & 1) * STAGE_B;
        int kt = c * 64;
#pragma unroll
        for (int i = 0; i < 4; i++) {
            int u = tid + (i & 1) * BLOCK;
            int row = u >> 3, ch = u & 7;
            int which = i >> 1;
            uint32_t dst = stb + (which ? OFF_AL : OFF_AH) + row * SROW_B + ch * 16;
            bool ok = (m0 + row) < rows;
            size_t slot = (size_t)row0 + m0 + (ok ? row : 0);
            const __nv_bfloat16* base = which ? g_H_lo : g_H_hi;
            cp16(dst, base + slot * FH + kt + ch * 8, ok ? 16 : 0);
        }
#pragma unroll
        for (int i = 0; i < 8; i++) {
            int u = tid + (i & 3) * BLOCK;
            int row = u >> 3, ch = u & 7;
            int which = i >> 2;
            uint32_t dst = stb + (which ? OFF_BL : OFF_BH) + row * SROW_B + ch * 16;
            const __nv_bfloat16* base = which ? Bl : Bh;
            cp16(dst, base + (size_t)row * FH + kt + ch * 8, 16);
        }
    };

    WarpAcc W;
#pragma unroll
    for (int mi = 0; mi < 4; mi++)
#pragma unroll
        for (int ni = 0; ni < 4; ni++)
#pragma unroll
            for (int r = 0; r < 4; r++) W.a[mi][ni][r] = 0.0f;

    int wm = (wid & 1) * 64, wn = (wid >> 1) * 32;

    load_stage(0); CP_COMMIT();
    for (int c = 0; c < NC; c++) {
        CP_WAIT0();
        __syncthreads();
        if (c + 1 < NC) load_stage(c + 1);
        CP_COMMIT();
        compute_stage(sb + (c & 1) * STAGE_B, lane, wm, wn, W);
    }

    const float* bias = proj_b + (size_t)e * DH;
#pragma unroll
    for (int mi = 0; mi < 4; mi++) {
#pragma unroll
        for (int rh = 0; rh < 2; rh++) {
            int m = wm + mi * 16 + (lane >> 2) + rh * 8;
            if (m0 + m >= rows) continue;
            size_t slot = (size_t)row0 + m0 + m;
            float w = g_wt[slot];
#pragma unroll
            for (int ni = 0; ni < 4; ni++) {
                int n = n0 + wn + ni * 8 + 2 * (lane & 3);
                float2 bb = *(const float2*)(bias + n);
                float v0 = w * (W.a[mi][ni][2 * rh + 0] + bb.x);
                float v1 = w * (W.a[mi][ni][2 * rh + 1] + bb.y);
                *(float2*)(g_O + slot * DH + n) = make_float2(v0, v1);
            }
        }
    }
}

// ---------------- combine (+ counter reset for next call) --------------------
__global__ void combine_kernel(float* __restrict__ out) {
    if (blockIdx.x == 0 && threadIdx.x < NEXP) {
        g_count[threadIdx.x] = 0;
        g_cursor[threadIdx.x] = 0;
    }
    int idx = blockIdx.x * blockDim.x + threadIdx.x;
    const int DQ = DH / 4;
    if (idx >= NTOK * DQ) return;
    int t = idx / DQ;
    int dq = idx - t * DQ;
    int s0 = g_slot[t * 2 + 0];
    int s1 = g_slot[t * 2 + 1];
    const float4* o0 = (const float4*)(g_O + (size_t)s0 * DH) + dq;
    const float4* o1 = (const float4*)(g_O + (size_t)s1 * DH) + dq;
    float4 a = *o0, b = *o1;
    ((float4*)(out + (size_t)t * DH))[dq] =
        make_float4(a.x + b.x, a.y + b.y, a.z + b.z, a.w + b.w);
}

// ---------------- launch -----------------------------------------------------
extern "C" void kernel_launch(void* const* d_in, const int* in_sizes, int n_in,
                              void* d_out, int out_size) {
    const float* x      = (const float*)d_in[0];
    const float* gate_w = (const float*)d_in[1];
    const float* fc_w   = (const float*)d_in[2];
    const float* fc_b   = (const float*)d_in[3];
    const float* proj_w = (const float*)d_in[4];
    const float* proj_b = (const float*)d_in[5];

    float* out = (float*)d_out;
    float* out_logits =
        (out_size >= NTOK * DH + NTOK * NEXP) ? (out + (size_t)NTOK * DH) : nullptr;

    cudaFuncSetAttribute(gemm1_mma, cudaFuncAttributeMaxDynamicSharedMemorySize, SMEM_G1);
    cudaFuncSetAttribute(gemm2_mma, cudaFuncAttributeMaxDynamicSharedMemorySize, SMEM_G2);

    __nv_bfloat16 *fh, *fl, *ph, *pl;
    cudaGetSymbolAddress((void**)&fh, g_fcwT_hi);
    cudaGetSymbolAddress((void**)&fl, g_fcwT_lo);
    cudaGetSymbolAddress((void**)&ph, g_prjT_hi);
    cudaGetSymbolAddress((void**)&pl, g_prjT_lo);

    // ncu profiles the 4th launch -> keep it gemm1.
    router_split_kernel<<<NTOK / 8, 256>>>(x, gate_w, out_logits);                 // 1
    scan_scatter_kernel<<<1, 1024>>>();                                            // 2
    transpose_split_kernel<<<dim3(FH / 32, DH / 32, NEXP), dim3(32, 8)>>>(fc_w, fh, fl, DH, FH);   // 3
    gemm1_mma<<<dim3(NTOK / 128, FH / 256, NEXP), BLOCK, SMEM_G1>>>(fc_b);         // 4  <- profiled
    transpose_split_kernel<<<dim3(DH / 32, FH / 32, NEXP), dim3(32, 8)>>>(proj_w, ph, pl, FH, DH); // 5
    gemm2_mma<<<dim3(NTOK / 128, DH / 256, NEXP), BLOCK, SMEM_G2>>>(proj_b);       // 6
    combine_kernel<<<(NTOK * (DH / 4) + 255) / 256, 256>>>(out);                   // 7

    (void)n_in; (void)in_sizes;
}

// round 9
// speedup vs baseline: 1.1646x; 1.0387x over previous
#include <cuda_runtime.h>
#include <cuda_bf16.h>
#include <math.h>
#include <stdint.h>

// Problem constants
#define NEXP 8
#define TOPK 2
#define DH   1024
#define FH   4096
#define NTOK 4096
#define NSLOT (NTOK * TOPK)   // 8192

// ---------------- scratch (static __device__ — no allocations) -------------
__device__ __nv_bfloat16 g_X_hi[(size_t)NTOK * DH];
__device__ __nv_bfloat16 g_X_lo[(size_t)NTOK * DH];
__device__ __nv_bfloat16 g_fcwT_hi[(size_t)NEXP * FH * DH];  // [e][n(F)][k(D)]
__device__ __nv_bfloat16 g_fcwT_lo[(size_t)NEXP * FH * DH];
__device__ __nv_bfloat16 g_prjT_hi[(size_t)NEXP * DH * FH];  // [e][n(D)][k(F)]
__device__ __nv_bfloat16 g_prjT_lo[(size_t)NEXP * DH * FH];
__device__ __nv_bfloat16 g_H_hi[(size_t)NSLOT * FH];
__device__ __nv_bfloat16 g_H_lo[(size_t)NSLOT * FH];
__device__ float g_O[(size_t)NSLOT * DH];
__device__ int   g_count[NEXP];     // statically zero; re-zeroed by combine
__device__ int   g_cursor[NEXP];
__device__ int   g_off[NEXP + 1];
__device__ int   g_eid[NSLOT];
__device__ float g_wk[NSLOT];
__device__ int   g_tok[NSLOT];
__device__ float g_wt[NSLOT];
__device__ int   g_slot[NSLOT];

// ---------------- generic-PTX helpers ---------------------------------------
__device__ __forceinline__ uint32_t smem_u32(const void* p) {
    uint32_t a;
    asm("{ .reg .u64 t; cvta.to.shared.u64 t, %1; cvt.u32.u64 %0, t; }" : "=r"(a) : "l"(p));
    return a;
}
__device__ __forceinline__ void cp16(uint32_t dst, const void* src, int srcsize) {
    asm volatile("cp.async.cg.shared.global [%0], [%1], 16, %2;"
                 :: "r"(dst), "l"(src), "r"(srcsize) : "memory");
}
#define CP_COMMIT() asm volatile("cp.async.commit_group;" ::: "memory")
#define CP_WAIT0()  asm volatile("cp.async.wait_group 0;" ::: "memory")

__device__ __forceinline__ void ldsm_x4(uint32_t* r, uint32_t addr) {
    asm volatile("ldmatrix.sync.aligned.m8n8.x4.shared.b16 {%0,%1,%2,%3}, [%4];"
                 : "=r"(r[0]), "=r"(r[1]), "=r"(r[2]), "=r"(r[3]) : "r"(addr));
}
__device__ __forceinline__ void mma16816(float* d, const uint32_t* a, uint32_t b0, uint32_t b1) {
    asm volatile(
        "mma.sync.aligned.m16n8k16.row.col.f32.bf16.bf16.f32 "
        "{%0,%1,%2,%3}, {%4,%5,%6,%7}, {%8,%9}, {%0,%1,%2,%3};"
        : "+f"(d[0]), "+f"(d[1]), "+f"(d[2]), "+f"(d[3])
        : "r"(a[0]), "r"(a[1]), "r"(a[2]), "r"(a[3]), "r"(b0), "r"(b1));
}

__device__ __forceinline__ float gelu_new(float v) {
    const float c = 0.7978845608028654f;
    float u = c * (v + 0.044715f * v * v * v);
    return 0.5f * v * (1.0f + tanhf(u));
}
__device__ __forceinline__ uint32_t pack2(__nv_bfloat16 a, __nv_bfloat16 b) {
    return (uint32_t)__bfloat16_as_ushort(a) | ((uint32_t)__bfloat16_as_ushort(b) << 16);
}
__device__ __forceinline__ void split4(float4 v, uint2& hv, uint2& lv) {
    __nv_bfloat16 h0 = __float2bfloat16(v.x), h1 = __float2bfloat16(v.y);
    __nv_bfloat16 h2 = __float2bfloat16(v.z), h3 = __float2bfloat16(v.w);
    hv.x = pack2(h0, h1); hv.y = pack2(h2, h3);
    lv.x = pack2(__float2bfloat16(v.x - __bfloat162float(h0)),
                 __float2bfloat16(v.y - __bfloat162float(h1)));
    lv.y = pack2(__float2bfloat16(v.z - __bfloat162float(h2)),
                 __float2bfloat16(v.w - __bfloat162float(h3)));
}

// SMEM tile geometry: K-stage = 64, row = 144 B (128 B data + 16 B pad)
#define SROW_B   144
#define OFF_AH   0
#define OFF_AL   18432              // 128 rows * 144
#define OFF_BH   36864
#define OFF_BL   73728              // Bh is 256 rows * 144 = 36864
#define STAGE_B  110592             // 36864 + 73728
#define NSTAGE   2
#define SMEM_G1  (NSTAGE * STAGE_B + 512)   // 221696
#define SMEM_G2  (NSTAGE * STAGE_B)
#define BLOCK    512

// ---------------- kernel 1: router + gate logits + x hi/lo split ------------
__global__ void router_split_kernel(const float* __restrict__ x,
                                    const float* __restrict__ gate_w,
                                    float* __restrict__ out_logits) {
    int warp = (blockIdx.x * blockDim.x + threadIdx.x) >> 5;
    int lane = threadIdx.x & 31;
    if (warp >= NTOK) return;
    const float* xp = x + (size_t)warp * DH;
    float acc[NEXP];
#pragma unroll
    for (int e = 0; e < NEXP; e++) acc[e] = 0.0f;
#pragma unroll
    for (int i = 0; i < DH / 128; i++) {
        int d = i * 128 + lane * 4;
        float4 v = *(const float4*)(xp + d);
        uint2 hv, lv; split4(v, hv, lv);
        *(uint2*)(g_X_hi + (size_t)warp * DH + d) = hv;
        *(uint2*)(g_X_lo + (size_t)warp * DH + d) = lv;
        const float* gw = gate_w + (size_t)d * NEXP;
#pragma unroll
        for (int e = 0; e < NEXP; e++)
            acc[e] += v.x * gw[e] + v.y * gw[NEXP + e]
                    + v.z * gw[2 * NEXP + e] + v.w * gw[3 * NEXP + e];
    }
#pragma unroll
    for (int e = 0; e < NEXP; e++)
#pragma unroll
        for (int o = 16; o > 0; o >>= 1)
            acc[e] += __shfl_xor_sync(0xffffffffu, acc[e], o);
    if (lane == 0) {
        if (out_logits)
#pragma unroll
            for (int e = 0; e < NEXP; e++) out_logits[warp * NEXP + e] = acc[e];
        int e0 = 0;
#pragma unroll
        for (int e = 1; e < NEXP; e++) if (acc[e] > acc[e0]) e0 = e;
        int e1 = (e0 == 0) ? 1 : 0;
#pragma unroll
        for (int e = 0; e < NEXP; e++) if (e != e0 && acc[e] > acc[e1]) e1 = e;
        float dlt = expf(acc[e1] - acc[e0]);
        float w0 = 1.0f / (1.0f + dlt);
        float w1 = dlt / (1.0f + dlt);
        g_eid[warp * 2 + 0] = e0; g_eid[warp * 2 + 1] = e1;
        g_wk [warp * 2 + 0] = w0; g_wk [warp * 2 + 1] = w1;
        atomicAdd(&g_count[e0], 1);
        atomicAdd(&g_count[e1], 1);
    }
}

// ---------------- kernel 2: fused scan + scatter (single block) --------------
__global__ void scan_scatter_kernel() {
    if (threadIdx.x == 0) {
        int acc = 0; g_off[0] = 0;
#pragma unroll
        for (int e = 0; e < NEXP; e++) { acc += g_count[e]; g_off[e + 1] = acc; }
    }
    __syncthreads();
    for (int t = threadIdx.x; t < NTOK; t += blockDim.x) {
#pragma unroll
        for (int k = 0; k < TOPK; k++) {
            int e = g_eid[t * 2 + k];
            int pos = g_off[e] + atomicAdd(&g_cursor[e], 1);
            g_tok[pos] = t;
            g_wt[pos]  = g_wk[t * 2 + k];
            g_slot[t * 2 + k] = pos;
        }
    }
}

// ------------- weight transpose + bf16 hi/lo split (vectorized stores) -------
__global__ __launch_bounds__(256)
void transpose_split_kernel(const float* __restrict__ src,
                            __nv_bfloat16* __restrict__ dh,
                            __nv_bfloat16* __restrict__ dl,
                            int K, int N) {
    __shared__ float t[32][33];
    int e = blockIdx.z;
    src += (size_t)e * K * N;
    dh  += (size_t)e * K * N;
    dl  += (size_t)e * K * N;
    int n0 = blockIdx.x * 32, k0 = blockIdx.y * 32;
    int xx = threadIdx.x, yy = threadIdx.y;  // (32, 8)
    int tid = yy * 32 + xx;
#pragma unroll
    for (int r = 0; r < 4; r++) {
        int k = yy + r * 8;
        t[k][xx] = src[(size_t)(k0 + k) * N + n0 + xx];
    }
    __syncthreads();
#pragma unroll
    for (int it = 0; it < 2; it++) {
        int j = it * 256 + tid;
        int n = j >> 4, kp = j & 15;
        float v0 = t[2 * kp][n], v1 = t[2 * kp + 1][n];
        __nv_bfloat16 h0 = __float2bfloat16(v0), h1 = __float2bfloat16(v1);
        __nv_bfloat16 l0 = __float2bfloat16(v0 - __bfloat162float(h0));
        __nv_bfloat16 l1 = __float2bfloat16(v1 - __bfloat162float(h1));
        size_t o = (size_t)(n0 + n) * K + k0 + 2 * kp;
        *(uint32_t*)(dh + o) = pack2(h0, h1);
        *(uint32_t*)(dl + o) = pack2(l0, l1);
    }
}

// ---------------- warp-level 64x32 3-pass compute over one 64-wide stage ----
// Interleaves load-issue chunks (for the NEXT stage) between k-quarters.
struct WarpAcc { float a[4][4][4]; };   // [mi][nfrag][frag]

template <typename F>
__device__ __forceinline__ void compute_stage(uint32_t stb, int lane, int wm, int wn,
                                              WarpAcc& W, F&& issue_chunk) {
#pragma unroll
    for (int q = 0; q < 4; q++) {
        issue_chunk(q);                     // 3 cp16/thread for next stage
        int kk = q * 16;
        uint32_t ah[4][4], al[4][4];
        uint32_t aoff = stb + OFF_AH
                      + (uint32_t)(wm + (lane & 15)) * SROW_B
                      + (uint32_t)(kk + ((lane >> 4) << 3)) * 2;
#pragma unroll
        for (int mi = 0; mi < 4; mi++) {
            ldsm_x4(ah[mi], aoff + mi * 16 * SROW_B);
            ldsm_x4(al[mi], aoff + mi * 16 * SROW_B + (OFF_AL - OFF_AH));
        }
        int bgrp = lane >> 3;
        uint32_t boff = stb + OFF_BH
                      + (uint32_t)(wn + (lane & 7) + ((bgrp & 2) << 2)) * SROW_B
                      + (uint32_t)(kk + ((bgrp & 1) << 3)) * 2;
#pragma unroll
        for (int p = 0; p < 2; p++) {           // n-frag pair (2p, 2p+1)
            uint32_t th[4], tl[4];
            ldsm_x4(th, boff + p * 16 * SROW_B);
            ldsm_x4(tl, boff + p * 16 * SROW_B + (OFF_BL - OFF_BH));
#pragma unroll
            for (int mi = 0; mi < 4; mi++) {
                mma16816(W.a[mi][2 * p],     ah[mi], th[0], th[1]);
                mma16816(W.a[mi][2 * p + 1], ah[mi], th[2], th[3]);
            }
#pragma unroll
            for (int mi = 0; mi < 4; mi++) {
                mma16816(W.a[mi][2 * p],     ah[mi], tl[0], tl[1]);
                mma16816(W.a[mi][2 * p + 1], ah[mi], tl[2], tl[3]);
            }
#pragma unroll
            for (int mi = 0; mi < 4; mi++) {
                mma16816(W.a[mi][2 * p],     al[mi], th[0], th[1]);
                mma16816(W.a[mi][2 * p + 1], al[mi], th[2], th[3]);
            }
        }
    }
}

// ---------------- GEMM1: H = gelu(x@fc_w + b), 128x256 tile, KC=64 ----------
__global__ __launch_bounds__(BLOCK, 1)
void gemm1_mma(const float* __restrict__ fc_b) {
    int e = blockIdx.z;
    int row0 = g_off[e];
    int rows = g_off[e + 1] - row0;
    int m0 = blockIdx.x * 128;
    if (m0 >= rows) return;
    int n0 = blockIdx.y * 256;

    extern __shared__ char smem[];
    uint32_t sb = smem_u32(smem);
    int tid = threadIdx.x, wid = tid >> 5, lane = tid & 31;

    int* s_tok = (int*)(smem + NSTAGE * STAGE_B);
    if (tid < 128) s_tok[tid] = (m0 + tid < rows) ? g_tok[row0 + m0 + tid] : -1;
    __syncthreads();

    const __nv_bfloat16* Bh = g_fcwT_hi + (size_t)e * FH * DH + (size_t)n0 * DH;
    const __nv_bfloat16* Bl = g_fcwT_lo + (size_t)e * FH * DH + (size_t)n0 * DH;

    const int NC = DH / 64;   // 16 stages

    // chunk q of stage c: A iter q + B iters 2q, 2q+1  (3 cp16/thread)
    auto issue = [&](int c, int q) {
        uint32_t stb = sb + (c & 1) * STAGE_B;
        int kt = c * 64;
        {   // A part
            int u = tid + (q & 1) * BLOCK;
            int row = u >> 3, ch = u & 7;
            int which = q >> 1;   // 0 hi, 1 lo
            uint32_t dst = stb + (which ? OFF_AL : OFF_AH) + row * SROW_B + ch * 16;
            int t = s_tok[row];
            const __nv_bfloat16* base = which ? g_X_lo : g_X_hi;
            cp16(dst, base + (size_t)(t < 0 ? 0 : t) * DH + kt + ch * 8, t < 0 ? 0 : 16);
        }
#pragma unroll
        for (int s = 0; s < 2; s++) {   // B parts: i = 2q + s
            int i = 2 * q + s;
            int u = tid + (i & 3) * BLOCK;
            int row = u >> 3, ch = u & 7;
            int which = i >> 2;
            uint32_t dst = stb + (which ? OFF_BL : OFF_BH) + row * SROW_B + ch * 16;
            const __nv_bfloat16* base = which ? Bl : Bh;
            cp16(dst, base + (size_t)row * DH + kt + ch * 8, 16);
        }
    };

    WarpAcc W;
#pragma unroll
    for (int mi = 0; mi < 4; mi++)
#pragma unroll
        for (int ni = 0; ni < 4; ni++)
#pragma unroll
            for (int r = 0; r < 4; r++) W.a[mi][ni][r] = 0.0f;

    int wm = (wid & 1) * 64, wn = (wid >> 1) * 32;

#pragma unroll
    for (int q = 0; q < 4; q++) issue(0, q);
    CP_COMMIT();
    for (int c = 0; c < NC; c++) {
        CP_WAIT0();
        __syncthreads();
        bool more = (c + 1 < NC);
        compute_stage(sb + (c & 1) * STAGE_B, lane, wm, wn, W,
                      [&](int q) { if (more) issue(c + 1, q); });
        CP_COMMIT();
    }

    const float* bias = fc_b + (size_t)e * FH;
#pragma unroll
    for (int mi = 0; mi < 4; mi++) {
#pragma unroll
        for (int rh = 0; rh < 2; rh++) {
            int m = wm + mi * 16 + (lane >> 2) + rh * 8;
            if (m0 + m >= rows) continue;
            size_t slot = (size_t)row0 + m0 + m;
#pragma unroll
            for (int ni = 0; ni < 4; ni++) {
                int n = n0 + wn + ni * 8 + 2 * (lane & 3);
                float2 bb = *(const float2*)(bias + n);
                float v0 = gelu_new(W.a[mi][ni][2 * rh + 0] + bb.x);
                float v1 = gelu_new(W.a[mi][ni][2 * rh + 1] + bb.y);
                __nv_bfloat16 h0 = __float2bfloat16(v0), h1 = __float2bfloat16(v1);
                __nv_bfloat16 l0 = __float2bfloat16(v0 - __bfloat162float(h0));
                __nv_bfloat16 l1 = __float2bfloat16(v1 - __bfloat162float(h1));
                *(uint32_t*)(g_H_hi + slot * FH + n) = pack2(h0, h1);
                *(uint32_t*)(g_H_lo + slot * FH + n) = pack2(l0, l1);
            }
        }
    }
}

// ---------------- GEMM2: O = wt * (H@proj_w + b), 128x256 tile, KC=64 -------
__global__ __launch_bounds__(BLOCK, 1)
void gemm2_mma(const float* __restrict__ proj_b) {
    int e = blockIdx.z;
    int row0 = g_off[e];
    int rows = g_off[e + 1] - row0;
    int m0 = blockIdx.x * 128;
    if (m0 >= rows) return;
    int n0 = blockIdx.y * 256;

    extern __shared__ char smem[];
    uint32_t sb = smem_u32(smem);
    int tid = threadIdx.x, wid = tid >> 5, lane = tid & 31;

    const __nv_bfloat16* Bh = g_prjT_hi + (size_t)e * DH * FH + (size_t)n0 * FH;
    const __nv_bfloat16* Bl = g_prjT_lo + (size_t)e * DH * FH + (size_t)n0 * FH;

    const int NC = FH / 64;   // 64 stages

    auto issue = [&](int c, int q) {
        uint32_t stb = sb + (c & 1) * STAGE_B;
        int kt = c * 64;
        {   // A part
            int u = tid + (q & 1) * BLOCK;
            int row = u >> 3, ch = u & 7;
            int which = q >> 1;
            uint32_t dst = stb + (which ? OFF_AL : OFF_AH) + row * SROW_B + ch * 16;
            bool ok = (m0 + row) < rows;
            size_t slot = (size_t)row0 + m0 + (ok ? row : 0);
            const __nv_bfloat16* base = which ? g_H_lo : g_H_hi;
            cp16(dst, base + slot * FH + kt + ch * 8, ok ? 16 : 0);
        }
#pragma unroll
        for (int s = 0; s < 2; s++) {
            int i = 2 * q + s;
            int u = tid + (i & 3) * BLOCK;
            int row = u >> 3, ch = u & 7;
            int which = i >> 2;
            uint32_t dst = stb + (which ? OFF_BL : OFF_BH) + row * SROW_B + ch * 16;
            const __nv_bfloat16* base = which ? Bl : Bh;
            cp16(dst, base + (size_t)row * FH + kt + ch * 8, 16);
        }
    };

    WarpAcc W;
#pragma unroll
    for (int mi = 0; mi < 4; mi++)
#pragma unroll
        for (int ni = 0; ni < 4; ni++)
#pragma unroll
            for (int r = 0; r < 4; r++) W.a[mi][ni][r] = 0.0f;

    int wm = (wid & 1) * 64, wn = (wid >> 1) * 32;

#pragma unroll
    for (int q = 0; q < 4; q++) issue(0, q);
    CP_COMMIT();
    for (int c = 0; c < NC; c++) {
        CP_WAIT0();
        __syncthreads();
        bool more = (c + 1 < NC);
        compute_stage(sb + (c & 1) * STAGE_B, lane, wm, wn, W,
                      [&](int q) { if (more) issue(c + 1, q); });
        CP_COMMIT();
    }

    const float* bias = proj_b + (size_t)e * DH;
#pragma unroll
    for (int mi = 0; mi < 4; mi++) {
#pragma unroll
        for (int rh = 0; rh < 2; rh++) {
            int m = wm + mi * 16 + (lane >> 2) + rh * 8;
            if (m0 + m >= rows) continue;
            size_t slot = (size_t)row0 + m0 + m;
            float w = g_wt[slot];
#pragma unroll
            for (int ni = 0; ni < 4; ni++) {
                int n = n0 + wn + ni * 8 + 2 * (lane & 3);
                float2 bb = *(const float2*)(bias + n);
                float v0 = w * (W.a[mi][ni][2 * rh + 0] + bb.x);
                float v1 = w * (W.a[mi][ni][2 * rh + 1] + bb.y);
                *(float2*)(g_O + slot * DH + n) = make_float2(v0, v1);
            }
        }
    }
}

// ---------------- combine (+ counter reset for next call) --------------------
__global__ void combine_kernel(float* __restrict__ out) {
    if (blockIdx.x == 0 && threadIdx.x < NEXP) {
        g_count[threadIdx.x] = 0;
        g_cursor[threadIdx.x] = 0;
    }
    int idx = blockIdx.x * blockDim.x + threadIdx.x;
    const int DQ = DH / 4;
    if (idx >= NTOK * DQ) return;
    int t = idx / DQ;
    int dq = idx - t * DQ;
    int s0 = g_slot[t * 2 + 0];
    int s1 = g_slot[t * 2 + 1];
    const float4* o0 = (const float4*)(g_O + (size_t)s0 * DH) + dq;
    const float4* o1 = (const float4*)(g_O + (size_t)s1 * DH) + dq;
    float4 a = *o0, b = *o1;
    ((float4*)(out + (size_t)t * DH))[dq] =
        make_float4(a.x + b.x, a.y + b.y, a.z + b.z, a.w + b.w);
}

// ---------------- launch -----------------------------------------------------
extern "C" void kernel_launch(void* const* d_in, const int* in_sizes, int n_in,
                              void* d_out, int out_size) {
    const float* x      = (const float*)d_in[0];
    const float* gate_w = (const float*)d_in[1];
    const float* fc_w   = (const float*)d_in[2];
    const float* fc_b   = (const float*)d_in[3];
    const float* proj_w = (const float*)d_in[4];
    const float* proj_b = (const float*)d_in[5];

    float* out = (float*)d_out;
    float* out_logits =
        (out_size >= NTOK * DH + NTOK * NEXP) ? (out + (size_t)NTOK * DH) : nullptr;

    cudaFuncSetAttribute(gemm1_mma, cudaFuncAttributeMaxDynamicSharedMemorySize, SMEM_G1);
    cudaFuncSetAttribute(gemm2_mma, cudaFuncAttributeMaxDynamicSharedMemorySize, SMEM_G2);

    __nv_bfloat16 *fh, *fl, *ph, *pl;
    cudaGetSymbolAddress((void**)&fh, g_fcwT_hi);
    cudaGetSymbolAddress((void**)&fl, g_fcwT_lo);
    cudaGetSymbolAddress((void**)&ph, g_prjT_hi);
    cudaGetSymbolAddress((void**)&pl, g_prjT_lo);

    // ncu profiles the 4th launch -> keep it gemm1.
    router_split_kernel<<<NTOK / 8, 256>>>(x, gate_w, out_logits);                 // 1
    scan_scatter_kernel<<<1, 1024>>>();                                            // 2
    transpose_split_kernel<<<dim3(FH / 32, DH / 32, NEXP), dim3(32, 8)>>>(fc_w, fh, fl, DH, FH);   // 3
    gemm1_mma<<<dim3(NTOK / 128, FH / 256, NEXP), BLOCK, SMEM_G1>>>(fc_b);         // 4  <- profiled
    transpose_split_kernel<<<dim3(DH / 32, FH / 32, NEXP), dim3(32, 8)>>>(proj_w, ph, pl, FH, DH); // 5
    gemm2_mma<<<dim3(NTOK / 128, DH / 256, NEXP), BLOCK, SMEM_G2>>>(proj_b);       // 6
    combine_kernel<<<(NTOK * (DH / 4) + 255) / 256, 256>>>(out);                   // 7

    (void)n_in; (void)in_sizes;
}

// round 10
// speedup vs baseline: 1.1766x; 1.0102x over previous
#include <cuda_runtime.h>
#include <cuda_bf16.h>
#include <math.h>
#include <stdint.h>

// Problem constants
#define NEXP 8
#define TOPK 2
#define DH   1024
#define FH   4096
#define NTOK 4096
#define NSLOT (NTOK * TOPK)   // 8192

// ---------------- scratch (static __device__ — no allocations) -------------
__device__ __nv_bfloat16 g_X_hi[(size_t)NTOK * DH];
__device__ __nv_bfloat16 g_X_lo[(size_t)NTOK * DH];
__device__ __nv_bfloat16 g_fcwT_hi[(size_t)NEXP * FH * DH];  // [e][n(F)][k(D)]
__device__ __nv_bfloat16 g_fcwT_lo[(size_t)NEXP * FH * DH];
__device__ __nv_bfloat16 g_prjT_hi[(size_t)NEXP * DH * FH];  // [e][n(D)][k(F)]
__device__ __nv_bfloat16 g_prjT_lo[(size_t)NEXP * DH * FH];
__device__ __nv_bfloat16 g_H_hi[(size_t)NSLOT * FH];
__device__ __nv_bfloat16 g_H_lo[(size_t)NSLOT * FH];
__device__ float g_O[(size_t)NSLOT * DH];
__device__ int   g_count[NEXP];     // statically zero; re-zeroed by combine
__device__ int   g_cursor[NEXP];
__device__ int   g_off[NEXP + 1];
__device__ int   g_eid[NSLOT];
__device__ float g_wk[NSLOT];
__device__ int   g_tok[NSLOT];
__device__ float g_wt[NSLOT];
__device__ int   g_slot[NSLOT];

// ---------------- generic-PTX helpers ---------------------------------------
__device__ __forceinline__ uint32_t smem_u32(const void* p) {
    uint32_t a;
    asm("{ .reg .u64 t; cvta.to.shared.u64 t, %1; cvt.u32.u64 %0, t; }" : "=r"(a) : "l"(p));
    return a;
}
__device__ __forceinline__ void cp16(uint32_t dst, const void* src, int srcsize) {
    asm volatile("cp.async.cg.shared.global [%0], [%1], 16, %2;"
                 :: "r"(dst), "l"(src), "r"(srcsize) : "memory");
}
#define CP_COMMIT() asm volatile("cp.async.commit_group;" ::: "memory")
#define CP_WAIT1()  asm volatile("cp.async.wait_group 1;" ::: "memory")

__device__ __forceinline__ void ldsm_x4(uint32_t* r, uint32_t addr) {
    asm volatile("ldmatrix.sync.aligned.m8n8.x4.shared.b16 {%0,%1,%2,%3}, [%4];"
                 : "=r"(r[0]), "=r"(r[1]), "=r"(r[2]), "=r"(r[3]) : "r"(addr));
}
__device__ __forceinline__ void mma16816(float* d, const uint32_t* a, uint32_t b0, uint32_t b1) {
    asm volatile(
        "mma.sync.aligned.m16n8k16.row.col.f32.bf16.bf16.f32 "
        "{%0,%1,%2,%3}, {%4,%5,%6,%7}, {%8,%9}, {%0,%1,%2,%3};"
        : "+f"(d[0]), "+f"(d[1]), "+f"(d[2]), "+f"(d[3])
        : "r"(a[0]), "r"(a[1]), "r"(a[2]), "r"(a[3]), "r"(b0), "r"(b1));
}

__device__ __forceinline__ float gelu_new(float v) {
    const float c = 0.7978845608028654f;
    float u = c * (v + 0.044715f * v * v * v);
    return 0.5f * v * (1.0f + tanhf(u));
}
__device__ __forceinline__ uint32_t pack2(__nv_bfloat16 a, __nv_bfloat16 b) {
    return (uint32_t)__bfloat16_as_ushort(a) | ((uint32_t)__bfloat16_as_ushort(b) << 16);
}
__device__ __forceinline__ void split4(float4 v, uint2& hv, uint2& lv) {
    __nv_bfloat16 h0 = __float2bfloat16(v.x), h1 = __float2bfloat16(v.y);
    __nv_bfloat16 h2 = __float2bfloat16(v.z), h3 = __float2bfloat16(v.w);
    hv.x = pack2(h0, h1); hv.y = pack2(h2, h3);
    lv.x = pack2(__float2bfloat16(v.x - __bfloat162float(h0)),
                 __float2bfloat16(v.y - __bfloat162float(h1)));
    lv.y = pack2(__float2bfloat16(v.z - __bfloat162float(h2)),
                 __float2bfloat16(v.w - __bfloat162float(h3)));
}

// SMEM tile geometry: K-stage = 64, row = 144 B (128 B data + 16 B pad)
#define SROW_B   144
#define OFF_AH   0
#define OFF_AL   18432              // 128 rows * 144
#define OFF_BH   36864
#define OFF_BL   73728              // Bh is 256 rows * 144 = 36864
#define STAGE_B  110592             // 36864 + 73728
#define NSTAGE   2
#define SMEM_G1  (NSTAGE * STAGE_B + 512)   // 221696
#define SMEM_G2  (NSTAGE * STAGE_B)
#define BLOCK    512

// ---------------- kernel 1: router + gate logits + x hi/lo split ------------
__global__ void router_split_kernel(const float* __restrict__ x,
                                    const float* __restrict__ gate_w,
                                    float* __restrict__ out_logits) {
    int warp = (blockIdx.x * blockDim.x + threadIdx.x) >> 5;
    int lane = threadIdx.x & 31;
    if (warp >= NTOK) return;
    const float* xp = x + (size_t)warp * DH;
    float acc[NEXP];
#pragma unroll
    for (int e = 0; e < NEXP; e++) acc[e] = 0.0f;
#pragma unroll
    for (int i = 0; i < DH / 128; i++) {
        int d = i * 128 + lane * 4;
        float4 v = *(const float4*)(xp + d);
        uint2 hv, lv; split4(v, hv, lv);
        *(uint2*)(g_X_hi + (size_t)warp * DH + d) = hv;
        *(uint2*)(g_X_lo + (size_t)warp * DH + d) = lv;
        const float* gw = gate_w + (size_t)d * NEXP;
#pragma unroll
        for (int e = 0; e < NEXP; e++)
            acc[e] += v.x * gw[e] + v.y * gw[NEXP + e]
                    + v.z * gw[2 * NEXP + e] + v.w * gw[3 * NEXP + e];
    }
#pragma unroll
    for (int e = 0; e < NEXP; e++)
#pragma unroll
        for (int o = 16; o > 0; o >>= 1)
            acc[e] += __shfl_xor_sync(0xffffffffu, acc[e], o);
    if (lane == 0) {
        if (out_logits)
#pragma unroll
            for (int e = 0; e < NEXP; e++) out_logits[warp * NEXP + e] = acc[e];
        int e0 = 0;
#pragma unroll
        for (int e = 1; e < NEXP; e++) if (acc[e] > acc[e0]) e0 = e;
        int e1 = (e0 == 0) ? 1 : 0;
#pragma unroll
        for (int e = 0; e < NEXP; e++) if (e != e0 && acc[e] > acc[e1]) e1 = e;
        float dlt = expf(acc[e1] - acc[e0]);
        float w0 = 1.0f / (1.0f + dlt);
        float w1 = dlt / (1.0f + dlt);
        g_eid[warp * 2 + 0] = e0; g_eid[warp * 2 + 1] = e1;
        g_wk [warp * 2 + 0] = w0; g_wk [warp * 2 + 1] = w1;
        atomicAdd(&g_count[e0], 1);
        atomicAdd(&g_count[e1], 1);
    }
}

// ---------------- kernel 2: fused scan + scatter (single block) --------------
__global__ void scan_scatter_kernel() {
    if (threadIdx.x == 0) {
        int acc = 0; g_off[0] = 0;
#pragma unroll
        for (int e = 0; e < NEXP; e++) { acc += g_count[e]; g_off[e + 1] = acc; }
    }
    __syncthreads();
    for (int t = threadIdx.x; t < NTOK; t += blockDim.x) {
#pragma unroll
        for (int k = 0; k < TOPK; k++) {
            int e = g_eid[t * 2 + k];
            int pos = g_off[e] + atomicAdd(&g_cursor[e], 1);
            g_tok[pos] = t;
            g_wt[pos]  = g_wk[t * 2 + k];
            g_slot[t * 2 + k] = pos;
        }
    }
}

// ------------- weight transpose + bf16 hi/lo split (vectorized stores) -------
__global__ __launch_bounds__(256)
void transpose_split_kernel(const float* __restrict__ src,
                            __nv_bfloat16* __restrict__ dh,
                            __nv_bfloat16* __restrict__ dl,
                            int K, int N) {
    __shared__ float t[32][33];
    int e = blockIdx.z;
    src += (size_t)e * K * N;
    dh  += (size_t)e * K * N;
    dl  += (size_t)e * K * N;
    int n0 = blockIdx.x * 32, k0 = blockIdx.y * 32;
    int xx = threadIdx.x, yy = threadIdx.y;  // (32, 8)
    int tid = yy * 32 + xx;
#pragma unroll
    for (int r = 0; r < 4; r++) {
        int k = yy + r * 8;
        t[k][xx] = src[(size_t)(k0 + k) * N + n0 + xx];
    }
    __syncthreads();
#pragma unroll
    for (int it = 0; it < 2; it++) {
        int j = it * 256 + tid;
        int n = j >> 4, kp = j & 15;
        float v0 = t[2 * kp][n], v1 = t[2 * kp + 1][n];
        __nv_bfloat16 h0 = __float2bfloat16(v0), h1 = __float2bfloat16(v1);
        __nv_bfloat16 l0 = __float2bfloat16(v0 - __bfloat162float(h0));
        __nv_bfloat16 l1 = __float2bfloat16(v1 - __bfloat162float(h1));
        size_t o = (size_t)(n0 + n) * K + k0 + 2 * kp;
        *(uint32_t*)(dh + o) = pack2(h0, h1);
        *(uint32_t*)(dl + o) = pack2(l0, l1);
    }
}

// ---------------- warp-level 64x32 3-pass compute over one 32-wide HALF -----
// Interleaves load-issue parts (for the NEXT stage's same half) per quarter.
struct WarpAcc { float a[4][4][4]; };   // [mi][nfrag][frag]

template <typename F>
__device__ __forceinline__ void compute_half(uint32_t stb, int lane, int wm, int wn,
                                             int h, WarpAcc& W, F&& issue_part) {
#pragma unroll
    for (int qq = 0; qq < 2; qq++) {
        issue_part(qq);                     // 3 cp16/thread of next-stage half h
        int kk = h * 32 + qq * 16;
        uint32_t ah[4][4], al[4][4];
        uint32_t aoff = stb + OFF_AH
                      + (uint32_t)(wm + (lane & 15)) * SROW_B
                      + (uint32_t)(kk + ((lane >> 4) << 3)) * 2;
#pragma unroll
        for (int mi = 0; mi < 4; mi++) {
            ldsm_x4(ah[mi], aoff + mi * 16 * SROW_B);
            ldsm_x4(al[mi], aoff + mi * 16 * SROW_B + (OFF_AL - OFF_AH));
        }
        int bgrp = lane >> 3;
        uint32_t boff = stb + OFF_BH
                      + (uint32_t)(wn + (lane & 7) + ((bgrp & 2) << 2)) * SROW_B
                      + (uint32_t)(kk + ((bgrp & 1) << 3)) * 2;
#pragma unroll
        for (int p = 0; p < 2; p++) {           // n-frag pair (2p, 2p+1)
            uint32_t th[4], tl[4];
            ldsm_x4(th, boff + p * 16 * SROW_B);
            ldsm_x4(tl, boff + p * 16 * SROW_B + (OFF_BL - OFF_BH));
#pragma unroll
            for (int mi = 0; mi < 4; mi++) {
                mma16816(W.a[mi][2 * p],     ah[mi], th[0], th[1]);
                mma16816(W.a[mi][2 * p + 1], ah[mi], th[2], th[3]);
            }
#pragma unroll
            for (int mi = 0; mi < 4; mi++) {
                mma16816(W.a[mi][2 * p],     ah[mi], tl[0], tl[1]);
                mma16816(W.a[mi][2 * p + 1], ah[mi], tl[2], tl[3]);
            }
#pragma unroll
            for (int mi = 0; mi < 4; mi++) {
                mma16816(W.a[mi][2 * p],     al[mi], th[0], th[1]);
                mma16816(W.a[mi][2 * p + 1], al[mi], th[2], th[3]);
            }
        }
    }
}

// ---------------- GEMM1: H = gelu(x@fc_w + b), 128x256 tile, KC=64 ----------
__global__ __launch_bounds__(BLOCK, 1)
void gemm1_mma(const float* __restrict__ fc_b) {
    int e = blockIdx.z;
    int row0 = g_off[e];
    int rows = g_off[e + 1] - row0;
    int m0 = blockIdx.x * 128;
    if (m0 >= rows) return;
    int n0 = blockIdx.y * 256;

    extern __shared__ char smem[];
    uint32_t sb = smem_u32(smem);
    int tid = threadIdx.x, wid = tid >> 5, lane = tid & 31;

    int* s_tok = (int*)(smem + NSTAGE * STAGE_B);
    if (tid < 128) s_tok[tid] = (m0 + tid < rows) ? g_tok[row0 + m0 + tid] : -1;
    __syncthreads();

    const __nv_bfloat16* Bh = g_fcwT_hi + (size_t)e * FH * DH + (size_t)n0 * DH;
    const __nv_bfloat16* Bl = g_fcwT_lo + (size_t)e * FH * DH + (size_t)n0 * DH;

    const int NC = DH / 64;   // 16 stages

    // half h of stage c, part ∈ {0,1}: part0 = A-hi + B-hi, part1 = A-lo + B-lo
    // each part = 3 cp16/thread; a committed group per half = 6 cp16/thread.
    auto issue = [&](int c, int h, int part) {
        uint32_t stb = sb + (c & 1) * STAGE_B;
        int kt = c * 64 + h * 32;
        uint32_t cb = (uint32_t)h * 64;   // byte column offset within row
        {   // A: 128 rows x 4 chunks = 512 sites (1/thread)
            int row = tid >> 2, ch = tid & 3;
            int t = s_tok[row];
            uint32_t dst = stb + (part ? OFF_AL : OFF_AH) + row * SROW_B + cb + ch * 16;
            const __nv_bfloat16* base = part ? g_X_lo : g_X_hi;
            cp16(dst, base + (size_t)(t < 0 ? 0 : t) * DH + kt + ch * 8, t < 0 ? 0 : 16);
        }
#pragma unroll
        for (int i = 0; i < 2; i++) {   // B: 256 rows x 4 chunks = 1024 sites (2/thread)
            int u = tid + i * BLOCK;
            int row = u >> 2, ch = u & 3;
            uint32_t dst = stb + (part ? OFF_BL : OFF_BH) + row * SROW_B + cb + ch * 16;
            const __nv_bfloat16* base = part ? Bl : Bh;
            cp16(dst, base + (size_t)row * DH + kt + ch * 8, 16);
        }
    };

    WarpAcc W;
#pragma unroll
    for (int mi = 0; mi < 4; mi++)
#pragma unroll
        for (int ni = 0; ni < 4; ni++)
#pragma unroll
            for (int r = 0; r < 4; r++) W.a[mi][ni][r] = 0.0f;

    int wm = (wid & 1) * 64, wn = (wid >> 1) * 32;

    issue(0, 0, 0); issue(0, 0, 1); CP_COMMIT();   // group: stage0 half0
    issue(0, 1, 0); issue(0, 1, 1); CP_COMMIT();   // group: stage0 half1
    for (int c = 0; c < NC; c++) {
        bool more = (c + 1 < NC);
        uint32_t stb = sb + (c & 1) * STAGE_B;
        CP_WAIT1();            // half0(c) complete; half1(c) may be in flight
        __syncthreads();
        compute_half(stb, lane, wm, wn, 0, W,
                     [&](int part) { if (more) issue(c + 1, 0, part); });
        CP_COMMIT();           // group: half0(c+1)
        CP_WAIT1();            // half1(c) complete; half0(c+1) may be in flight
        __syncthreads();
        compute_half(stb, lane, wm, wn, 1, W,
                     [&](int part) { if (more) issue(c + 1, 1, part); });
        CP_COMMIT();           // group: half1(c+1)
    }

    const float* bias = fc_b + (size_t)e * FH;
#pragma unroll
    for (int mi = 0; mi < 4; mi++) {
#pragma unroll
        for (int rh = 0; rh < 2; rh++) {
            int m = wm + mi * 16 + (lane >> 2) + rh * 8;
            if (m0 + m >= rows) continue;
            size_t slot = (size_t)row0 + m0 + m;
#pragma unroll
            for (int ni = 0; ni < 4; ni++) {
                int n = n0 + wn + ni * 8 + 2 * (lane & 3);
                float2 bb = *(const float2*)(bias + n);
                float v0 = gelu_new(W.a[mi][ni][2 * rh + 0] + bb.x);
                float v1 = gelu_new(W.a[mi][ni][2 * rh + 1] + bb.y);
                __nv_bfloat16 h0 = __float2bfloat16(v0), h1 = __float2bfloat16(v1);
                __nv_bfloat16 l0 = __float2bfloat16(v0 - __bfloat162float(h0));
                __nv_bfloat16 l1 = __float2bfloat16(v1 - __bfloat162float(h1));
                *(uint32_t*)(g_H_hi + slot * FH + n) = pack2(h0, h1);
                *(uint32_t*)(g_H_lo + slot * FH + n) = pack2(l0, l1);
            }
        }
    }
}

// ---------------- GEMM2: O = wt * (H@proj_w + b), 128x256 tile, KC=64 -------
__global__ __launch_bounds__(BLOCK, 1)
void gemm2_mma(const float* __restrict__ proj_b) {
    int e = blockIdx.z;
    int row0 = g_off[e];
    int rows = g_off[e + 1] - row0;
    int m0 = blockIdx.x * 128;
    if (m0 >= rows) return;
    int n0 = blockIdx.y * 256;

    extern __shared__ char smem[];
    uint32_t sb = smem_u32(smem);
    int tid = threadIdx.x, wid = tid >> 5, lane = tid & 31;

    const __nv_bfloat16* Bh = g_prjT_hi + (size_t)e * DH * FH + (size_t)n0 * FH;
    const __nv_bfloat16* Bl = g_prjT_lo + (size_t)e * DH * FH + (size_t)n0 * FH;

    const int NC = FH / 64;   // 64 stages

    auto issue = [&](int c, int h, int part) {
        uint32_t stb = sb + (c & 1) * STAGE_B;
        int kt = c * 64 + h * 32;
        uint32_t cb = (uint32_t)h * 64;
        {   // A part
            int row = tid >> 2, ch = tid & 3;
            bool ok = (m0 + row) < rows;
            size_t slot = (size_t)row0 + m0 + (ok ? row : 0);
            uint32_t dst = stb + (part ? OFF_AL : OFF_AH) + row * SROW_B + cb + ch * 16;
            const __nv_bfloat16* base = part ? g_H_lo : g_H_hi;
            cp16(dst, base + slot * FH + kt + ch * 8, ok ? 16 : 0);
        }
#pragma unroll
        for (int i = 0; i < 2; i++) {
            int u = tid + i * BLOCK;
            int row = u >> 2, ch = u & 3;
            uint32_t dst = stb + (part ? OFF_BL : OFF_BH) + row * SROW_B + cb + ch * 16;
            const __nv_bfloat16* base = part ? Bl : Bh;
            cp16(dst, base + (size_t)row * FH + kt + ch * 8, 16);
        }
    };

    WarpAcc W;
#pragma unroll
    for (int mi = 0; mi < 4; mi++)
#pragma unroll
        for (int ni = 0; ni < 4; ni++)
#pragma unroll
            for (int r = 0; r < 4; r++) W.a[mi][ni][r] = 0.0f;

    int wm = (wid & 1) * 64, wn = (wid >> 1) * 32;

    issue(0, 0, 0); issue(0, 0, 1); CP_COMMIT();
    issue(0, 1, 0); issue(0, 1, 1); CP_COMMIT();
    for (int c = 0; c < NC; c++) {
        bool more = (c + 1 < NC);
        uint32_t stb = sb + (c & 1) * STAGE_B;
        CP_WAIT1();
        __syncthreads();
        compute_half(stb, lane, wm, wn, 0, W,
                     [&](int part) { if (more) issue(c + 1, 0, part); });
        CP_COMMIT();
        CP_WAIT1();
        __syncthreads();
        compute_half(stb, lane, wm, wn, 1, W,
                     [&](int part) { if (more) issue(c + 1, 1, part); });
        CP_COMMIT();
    }

    const float* bias = proj_b + (size_t)e * DH;
#pragma unroll
    for (int mi = 0; mi < 4; mi++) {
#pragma unroll
        for (int rh = 0; rh < 2; rh++) {
            int m = wm + mi * 16 + (lane >> 2) + rh * 8;
            if (m0 + m >= rows) continue;
            size_t slot = (size_t)row0 + m0 + m;
            float w = g_wt[slot];
#pragma unroll
            for (int ni = 0; ni < 4; ni++) {
                int n = n0 + wn + ni * 8 + 2 * (lane & 3);
                float2 bb = *(const float2*)(bias + n);
                float v0 = w * (W.a[mi][ni][2 * rh + 0] + bb.x);
                float v1 = w * (W.a[mi][ni][2 * rh + 1] + bb.y);
                *(float2*)(g_O + slot * DH + n) = make_float2(v0, v1);
            }
        }
    }
}

// ---------------- combine (+ counter reset for next call) --------------------
__global__ void combine_kernel(float* __restrict__ out) {
    if (blockIdx.x == 0 && threadIdx.x < NEXP) {
        g_count[threadIdx.x] = 0;
        g_cursor[threadIdx.x] = 0;
    }
    int idx = blockIdx.x * blockDim.x + threadIdx.x;
    const int DQ = DH / 4;
    if (idx >= NTOK * DQ) return;
    int t = idx / DQ;
    int dq = idx - t * DQ;
    int s0 = g_slot[t * 2 + 0];
    int s1 = g_slot[t * 2 + 1];
    const float4* o0 = (const float4*)(g_O + (size_t)s0 * DH) + dq;
    const float4* o1 = (const float4*)(g_O + (size_t)s1 * DH) + dq;
    float4 a = *o0, b = *o1;
    ((float4*)(out + (size_t)t * DH))[dq] =
        make_float4(a.x + b.x, a.y + b.y, a.z + b.z, a.w + b.w);
}

// ---------------- launch -----------------------------------------------------
extern "C" void kernel_launch(void* const* d_in, const int* in_sizes, int n_in,
                              void* d_out, int out_size) {
    const float* x      = (const float*)d_in[0];
    const float* gate_w = (const float*)d_in[1];
    const float* fc_w   = (const float*)d_in[2];
    const float* fc_b   = (const float*)d_in[3];
    const float* proj_w = (const float*)d_in[4];
    const float* proj_b = (const float*)d_in[5];

    float* out = (float*)d_out;
    float* out_logits =
        (out_size >= NTOK * DH + NTOK * NEXP) ? (out + (size_t)NTOK * DH) : nullptr;

    cudaFuncSetAttribute(gemm1_mma, cudaFuncAttributeMaxDynamicSharedMemorySize, SMEM_G1);
    cudaFuncSetAttribute(gemm2_mma, cudaFuncAttributeMaxDynamicSharedMemorySize, SMEM_G2);

    __nv_bfloat16 *fh, *fl, *ph, *pl;
    cudaGetSymbolAddress((void**)&fh, g_fcwT_hi);
    cudaGetSymbolAddress((void**)&fl, g_fcwT_lo);
    cudaGetSymbolAddress((void**)&ph, g_prjT_hi);
    cudaGetSymbolAddress((void**)&pl, g_prjT_lo);

    // ncu profiles the 4th launch -> keep it gemm1.
    router_split_kernel<<<NTOK / 8, 256>>>(x, gate_w, out_logits);                 // 1
    scan_scatter_kernel<<<1, 1024>>>();                                            // 2
    transpose_split_kernel<<<dim3(FH / 32, DH / 32, NEXP), dim3(32, 8)>>>(fc_w, fh, fl, DH, FH);   // 3
    gemm1_mma<<<dim3(NTOK / 128, FH / 256, NEXP), BLOCK, SMEM_G1>>>(fc_b);         // 4  <- profiled
    transpose_split_kernel<<<dim3(DH / 32, FH / 32, NEXP), dim3(32, 8)>>>(proj_w, ph, pl, FH, DH); // 5
    gemm2_mma<<<dim3(NTOK / 128, DH / 256, NEXP), BLOCK, SMEM_G2>>>(proj_b);       // 6
    combine_kernel<<<(NTOK * (DH / 4) + 255) / 256, 256>>>(out);                   // 7

    (void)n_in; (void)in_sizes;
}